// round 1
// baseline (speedup 1.0000x reference)
#include <cuda_runtime.h>
#include <cstdint>

// ---------------------------------------------------------------------------
// Problem constants
//   input:  [16, 64, 128, 128]  fp32
//   conv1:  1x1, 64 -> 256, BN+ReLU          -> c1   [16,256,128,128]
//   conv2:  3x3 pad1, 256 -> 128, BN+ReLU    -> c2   [16,128,128,128]
//   sobel:  depthwise 3x3 pad1 (summed kern) -> edge [16,128,128,128]
//   conv3:  3x3 pad1, 128 -> 64, BN+ReLU     -> out[:,64:128]
//   concat: out[:,0:64] = input
// ---------------------------------------------------------------------------

#define BATCH 16
#define HH 128
#define WW 128
#define HWSZ (HH * WW)          // 16384
#define C_IN 64
#define C1 256
#define C2 128
#define C3 64
#define EPSV 1e-5f

// Scratch (allocation-free: __device__ globals)
__device__ float g_c1[(size_t)BATCH * C1 * HWSZ];    // 256 MB
__device__ float g_c2[(size_t)BATCH * C2 * HWSZ];    // 128 MB
__device__ float g_edge[(size_t)BATCH * C2 * HWSZ];  // 128 MB

// ---------------------------------------------------------------------------
// Kernel 1: 1x1 conv (GEMM 256x64 applied per pixel) + BN + ReLU
// Block: 64 output channels x 64 pixels, 256 threads, thread = 4co x 4px
// ---------------------------------------------------------------------------
__global__ __launch_bounds__(256) void conv1x1_bn_relu(
    const float* __restrict__ x, const float* __restrict__ w,
    const float* __restrict__ bb, const float* __restrict__ gg,
    const float* __restrict__ be, const float* __restrict__ mm,
    const float* __restrict__ vv, float* __restrict__ out) {
    __shared__ float Xs[64][68];  // [ci][px]
    __shared__ float Ws[64][68];  // [ci][co]

    const int pxBase = blockIdx.x * 64;
    const int coBase = blockIdx.y * 64;
    const int b = blockIdx.z;
    const int tid = threadIdx.x;

    const float* xb = x + (size_t)b * C_IN * HWSZ;

    // Load X tile: 64 ci x 64 px (coalesced along px)
    #pragma unroll
    for (int i = tid; i < 64 * 64; i += 256) {
        int ci = i >> 6, px = i & 63;
        Xs[ci][px] = xb[(size_t)ci * HWSZ + pxBase + px];
    }
    // Load W tile: w1 layout [co][ci]; store transposed [ci][co]
    #pragma unroll
    for (int i = tid; i < 64 * 64; i += 256) {
        int co = i >> 6, ci = i & 63;
        Ws[ci][co] = w[(size_t)(coBase + co) * C_IN + ci];
    }
    __syncthreads();

    const int px0 = (tid & 15) * 4;
    const int co0 = (tid >> 4) * 4;

    float acc[4][4];
    #pragma unroll
    for (int o = 0; o < 4; o++)
        #pragma unroll
        for (int p = 0; p < 4; p++) acc[o][p] = 0.f;

    #pragma unroll 8
    for (int k = 0; k < 64; k++) {
        float4 xv = *(const float4*)&Xs[k][px0];
        float4 wv = *(const float4*)&Ws[k][co0];
        float xa[4] = {xv.x, xv.y, xv.z, xv.w};
        float wa[4] = {wv.x, wv.y, wv.z, wv.w};
        #pragma unroll
        for (int o = 0; o < 4; o++)
            #pragma unroll
            for (int p = 0; p < 4; p++)
                acc[o][p] = fmaf(wa[o], xa[p], acc[o][p]);
    }

    #pragma unroll
    for (int o = 0; o < 4; o++) {
        int co = coBase + co0 + o;
        float s = __ldg(&gg[co]) * rsqrtf(__ldg(&vv[co]) + EPSV);
        float t = (__ldg(&bb[co]) - __ldg(&mm[co])) * s + __ldg(&be[co]);
        float4 r;
        r.x = fmaxf(fmaf(acc[o][0], s, t), 0.f);
        r.y = fmaxf(fmaf(acc[o][1], s, t), 0.f);
        r.z = fmaxf(fmaf(acc[o][2], s, t), 0.f);
        r.w = fmaxf(fmaf(acc[o][3], s, t), 0.f);
        *(float4*)&out[((size_t)b * C1 + co) * HWSZ + pxBase + px0] = r;
    }
}

// ---------------------------------------------------------------------------
// Kernel 2/4: 3x3 conv pad=1 + BN + ReLU (templated on Cin)
// Block: 64 oc x (16x16 px) tile, 256 threads, thread = 8 oc x 8 px (row chunk)
// Loop over input channels in chunks of 8, staged in smem.
// ---------------------------------------------------------------------------
template <int CIN>
__global__ __launch_bounds__(256, 2) void conv3x3_bn_relu(
    const float* __restrict__ in, const float* __restrict__ w,
    const float* __restrict__ bb, const float* __restrict__ gg,
    const float* __restrict__ be, const float* __restrict__ mm,
    const float* __restrict__ vv, float* __restrict__ out,
    int outCstride, int outCoff) {
    __shared__ float Xs[8][18][20];   // [ic][y][x], padded row stride 20
    __shared__ float Ws[8][9][68];    // [ic][tap][oc], oc dim padded to 68

    const int tile = blockIdx.x;           // 8x8 spatial tiles of 16x16
    const int ty0 = (tile >> 3) * 16;
    const int tx0 = (tile & 7) * 16;
    const int ocBase = blockIdx.y * 64;
    const int b = blockIdx.z;
    const int tid = threadIdx.x;

    const int oc0 = (tid >> 5) * 8;        // 8 groups of 8 output channels
    const int pg = tid & 31;               // 32 pixel groups of 8 px
    const int prow = pg >> 1;              // 0..15
    const int pcol = (pg & 1) * 8;         // 0 or 8

    float acc[8][8];
    #pragma unroll
    for (int o = 0; o < 8; o++)
        #pragma unroll
        for (int p = 0; p < 8; p++) acc[o][p] = 0.f;

    const float* inb = in + (size_t)b * CIN * HWSZ;

    for (int cc = 0; cc < CIN / 8; cc++) {
        // --- load input tile 8 ic x 18 x 18 (with halo + zero pad) ---
        for (int i = tid; i < 8 * 18 * 18; i += 256) {
            int ic = i / 324;
            int r = i - ic * 324;
            int yy = r / 18;
            int xx = r - yy * 18;
            int gy = ty0 - 1 + yy;
            int gx = tx0 - 1 + xx;
            float v = 0.f;
            if ((unsigned)gy < (unsigned)HH && (unsigned)gx < (unsigned)WW)
                v = inb[(size_t)(cc * 8 + ic) * HWSZ + gy * WW + gx];
            Xs[ic][yy][xx] = v;
        }
        // --- load weights 64 oc x 8 ic x 9 taps, transposed to [ic][tap][oc] ---
        for (int i = tid; i < 64 * 72; i += 256) {
            int oc = i / 72;
            int r = i - oc * 72;
            int ic = r / 9;
            int tap = r - ic * 9;
            Ws[ic][tap][oc] =
                w[((size_t)(ocBase + oc) * CIN + cc * 8 + ic) * 9 + tap];
        }
        __syncthreads();

        #pragma unroll 1
        for (int ic = 0; ic < 8; ++ic) {
            #pragma unroll
            for (int ky = 0; ky < 3; ++ky) {
                const float* xrow = &Xs[ic][prow + ky][pcol];
                float4 xa = *(const float4*)(xrow);
                float4 xbv = *(const float4*)(xrow + 4);
                float2 xc = *(const float2*)(xrow + 8);
                float xr[10] = {xa.x, xa.y, xa.z, xa.w,
                                xbv.x, xbv.y, xbv.z, xbv.w,
                                xc.x, xc.y};
                #pragma unroll
                for (int kx = 0; kx < 3; ++kx) {
                    const float* wrow = &Ws[ic][ky * 3 + kx][oc0];
                    float4 w0 = *(const float4*)(wrow);
                    float4 w1 = *(const float4*)(wrow + 4);
                    float wa[8] = {w0.x, w0.y, w0.z, w0.w,
                                   w1.x, w1.y, w1.z, w1.w};
                    #pragma unroll
                    for (int o = 0; o < 8; ++o)
                        #pragma unroll
                        for (int p = 0; p < 8; ++p)
                            acc[o][p] = fmaf(wa[o], xr[kx + p], acc[o][p]);
                }
            }
        }
        __syncthreads();
    }

    // --- epilogue: BN + ReLU, vectorized stores ---
    #pragma unroll
    for (int o = 0; o < 8; o++) {
        int oc = ocBase + oc0 + o;
        float s = __ldg(&gg[oc]) * rsqrtf(__ldg(&vv[oc]) + EPSV);
        float t = (__ldg(&bb[oc]) - __ldg(&mm[oc])) * s + __ldg(&be[oc]);
        float4 r0, r1;
        r0.x = fmaxf(fmaf(acc[o][0], s, t), 0.f);
        r0.y = fmaxf(fmaf(acc[o][1], s, t), 0.f);
        r0.z = fmaxf(fmaf(acc[o][2], s, t), 0.f);
        r0.w = fmaxf(fmaf(acc[o][3], s, t), 0.f);
        r1.x = fmaxf(fmaf(acc[o][4], s, t), 0.f);
        r1.y = fmaxf(fmaf(acc[o][5], s, t), 0.f);
        r1.z = fmaxf(fmaf(acc[o][6], s, t), 0.f);
        r1.w = fmaxf(fmaf(acc[o][7], s, t), 0.f);
        float* op = out + ((size_t)(b * outCstride + outCoff + oc) * HWSZ) +
                    (ty0 + prow) * WW + tx0 + pcol;
        *(float4*)op = r0;
        *(float4*)(op + 4) = r1;
    }
}

// ---------------------------------------------------------------------------
// Kernel 3: sobel depthwise (summed kernel), pad=1. Memory bound.
// Kernel (correlation):  [[ 2, 4, 4],
//                         [-2, 0, 2],
//                         [-4,-4,-2]]
// ---------------------------------------------------------------------------
__global__ __launch_bounds__(256) void sobel_dw(const float* __restrict__ in,
                                                float* __restrict__ out,
                                                int total) {
    int idx = blockIdx.x * 256 + threadIdx.x;
    if (idx >= total) return;
    int xw = idx & (WW - 1);
    int yh = (idx >> 7) & (HH - 1);
    const float* p = in + idx;
    bool up = yh > 0, dn = yh < HH - 1, lf = xw > 0, rt = xw < WW - 1;
    float s = 0.f;
    if (up) {
        if (lf) s = fmaf(2.f, p[-WW - 1], s);
        s = fmaf(4.f, p[-WW], s);
        if (rt) s = fmaf(4.f, p[-WW + 1], s);
    }
    if (lf) s = fmaf(-2.f, p[-1], s);
    if (rt) s = fmaf(2.f, p[1], s);
    if (dn) {
        if (lf) s = fmaf(-4.f, p[WW - 1], s);
        s = fmaf(-4.f, p[WW], s);
        if (rt) s = fmaf(-2.f, p[WW + 1], s);
    }
    out[idx] = s;
}

// ---------------------------------------------------------------------------
// Kernel 5: concat copy — out[:, 0:64] = input. Vectorized float4.
// in per-batch block: 64*HW floats; out per-batch block: 128*HW floats.
// ---------------------------------------------------------------------------
__global__ __launch_bounds__(256) void concat_copy(const float4* __restrict__ in,
                                                   float4* __restrict__ out) {
    int idx = blockIdx.x * 256 + threadIdx.x;  // 16 * 262144 total
    int b = idx >> 18;                         // 262144 = 64*HW/4
    int r = idx & 262143;
    out[(size_t)b * 524288 + r] = in[(size_t)b * 262144 + r];
}

// ---------------------------------------------------------------------------
extern "C" void kernel_launch(void* const* d_in, const int* in_sizes, int n_in,
                              void* d_out, int out_size) {
    const float* input = (const float*)d_in[0];
    const float* w1 = (const float*)d_in[1];
    const float* b1 = (const float*)d_in[2];
    const float* g1 = (const float*)d_in[3];
    const float* be1 = (const float*)d_in[4];
    const float* m1 = (const float*)d_in[5];
    const float* v1 = (const float*)d_in[6];
    const float* w2 = (const float*)d_in[7];
    const float* b2 = (const float*)d_in[8];
    const float* g2 = (const float*)d_in[9];
    const float* be2 = (const float*)d_in[10];
    const float* m2 = (const float*)d_in[11];
    const float* v2 = (const float*)d_in[12];
    const float* w3 = (const float*)d_in[13];
    const float* b3 = (const float*)d_in[14];
    const float* g3 = (const float*)d_in[15];
    const float* be3 = (const float*)d_in[16];
    const float* m3 = (const float*)d_in[17];
    const float* v3 = (const float*)d_in[18];
    float* out = (float*)d_out;

    float *c1, *c2, *edge;
    cudaGetSymbolAddress((void**)&c1, g_c1);
    cudaGetSymbolAddress((void**)&c2, g_c2);
    cudaGetSymbolAddress((void**)&edge, g_edge);

    // conv1: 1x1, 64->256, BN+ReLU
    conv1x1_bn_relu<<<dim3(HWSZ / 64, C1 / 64, BATCH), 256>>>(
        input, w1, b1, g1, be1, m1, v1, c1);

    // conv2: 3x3, 256->128, BN+ReLU
    conv3x3_bn_relu<C1><<<dim3(64, C2 / 64, BATCH), 256>>>(
        c1, w2, b2, g2, be2, m2, v2, c2, C2, 0);

    // sobel depthwise
    {
        int total = BATCH * C2 * HWSZ;
        sobel_dw<<<(total + 255) / 256, 256>>>(c2, edge, total);
    }

    // conv3: 3x3, 128->64, BN+ReLU -> out channels [64,128)
    conv3x3_bn_relu<C2><<<dim3(64, C3 / 64, BATCH), 256>>>(
        edge, w3, b3, g3, be3, m3, v3, out, 128, 64);

    // concat: out channels [0,64) = input
    concat_copy<<<BATCH * (C_IN * HWSZ / 4) / 256, 256>>>(
        (const float4*)input, (float4*)out);
}

// round 2
// speedup vs baseline: 1.9196x; 1.9196x over previous
#include <cuda_runtime.h>
#include <cstdint>

// ---------------------------------------------------------------------------
// Problem constants
//   input:  [16, 64, 128, 128]  fp32
//   conv1:  1x1, 64 -> 256, BN+ReLU          -> c1   [16,256,128,128]   (fp32 FFMA)
//   conv2:  3x3 pad1, 256 -> 128, BN+ReLU    -> c2   (TF32 mma.sync)
//   sobel:  depthwise 3x3 pad1 (summed kern) -> edge
//   conv3:  3x3 pad1, 128 -> 64, BN+ReLU     -> out[:,64:128] (TF32 mma.sync)
//   concat: out[:,0:64] = input
// ---------------------------------------------------------------------------

#define BATCH 16
#define HH 128
#define WW 128
#define HWSZ (HH * WW)
#define C_IN 64
#define C1 256
#define C2 128
#define C3 64
#define EPSV 1e-5f

__device__ float g_c1[(size_t)BATCH * C1 * HWSZ];
__device__ float g_c2[(size_t)BATCH * C2 * HWSZ];
__device__ float g_edge[(size_t)BATCH * C2 * HWSZ];

// ---------------------------------------------------------------------------
// helpers
// ---------------------------------------------------------------------------
__device__ __forceinline__ uint32_t f2tf32(float x) {
    uint32_t r;
    asm("cvt.rna.tf32.f32 %0, %1;" : "=r"(r) : "f"(x));
    return r;
}

__device__ __forceinline__ void mma_tf32(float c[4], const uint32_t a[4],
                                         uint32_t b0, uint32_t b1) {
    asm volatile(
        "mma.sync.aligned.m16n8k8.row.col.f32.tf32.tf32.f32 "
        "{%0,%1,%2,%3}, {%4,%5,%6,%7}, {%8,%9}, {%0,%1,%2,%3};"
        : "+f"(c[0]), "+f"(c[1]), "+f"(c[2]), "+f"(c[3])
        : "r"(a[0]), "r"(a[1]), "r"(a[2]), "r"(a[3]), "r"(b0), "r"(b1));
}

// ---------------------------------------------------------------------------
// Kernel 1: 1x1 conv (GEMM) + BN + ReLU (fp32, kept for accuracy)
// ---------------------------------------------------------------------------
__global__ __launch_bounds__(256) void conv1x1_bn_relu(
    const float* __restrict__ x, const float* __restrict__ w,
    const float* __restrict__ bb, const float* __restrict__ gg,
    const float* __restrict__ be, const float* __restrict__ mm,
    const float* __restrict__ vv, float* __restrict__ out) {
    __shared__ float Xs[64][68];
    __shared__ float Ws[64][68];

    const int pxBase = blockIdx.x * 64;
    const int coBase = blockIdx.y * 64;
    const int b = blockIdx.z;
    const int tid = threadIdx.x;

    const float* xb = x + (size_t)b * C_IN * HWSZ;

    #pragma unroll
    for (int i = tid; i < 64 * 64; i += 256) {
        int ci = i >> 6, px = i & 63;
        Xs[ci][px] = xb[(size_t)ci * HWSZ + pxBase + px];
    }
    #pragma unroll
    for (int i = tid; i < 64 * 64; i += 256) {
        int co = i >> 6, ci = i & 63;
        Ws[ci][co] = w[(size_t)(coBase + co) * C_IN + ci];
    }
    __syncthreads();

    const int px0 = (tid & 15) * 4;
    const int co0 = (tid >> 4) * 4;

    float acc[4][4];
    #pragma unroll
    for (int o = 0; o < 4; o++)
        #pragma unroll
        for (int p = 0; p < 4; p++) acc[o][p] = 0.f;

    #pragma unroll 8
    for (int k = 0; k < 64; k++) {
        float4 xv = *(const float4*)&Xs[k][px0];
        float4 wv = *(const float4*)&Ws[k][co0];
        float xa[4] = {xv.x, xv.y, xv.z, xv.w};
        float wa[4] = {wv.x, wv.y, wv.z, wv.w};
        #pragma unroll
        for (int o = 0; o < 4; o++)
            #pragma unroll
            for (int p = 0; p < 4; p++)
                acc[o][p] = fmaf(wa[o], xa[p], acc[o][p]);
    }

    #pragma unroll
    for (int o = 0; o < 4; o++) {
        int co = coBase + co0 + o;
        float s = __ldg(&gg[co]) * rsqrtf(__ldg(&vv[co]) + EPSV);
        float t = (__ldg(&bb[co]) - __ldg(&mm[co])) * s + __ldg(&be[co]);
        float4 r;
        r.x = fmaxf(fmaf(acc[o][0], s, t), 0.f);
        r.y = fmaxf(fmaf(acc[o][1], s, t), 0.f);
        r.z = fmaxf(fmaf(acc[o][2], s, t), 0.f);
        r.w = fmaxf(fmaf(acc[o][3], s, t), 0.f);
        *(float4*)&out[((size_t)b * C1 + co) * HWSZ + pxBase + px0] = r;
    }
}

// ---------------------------------------------------------------------------
// Kernels 2/4: 3x3 conv + BN + ReLU via TF32 mma.sync m16n8k8
//
// CTA: 64 oc x 256 px (2 output rows y0, y0+1 of one batch image), 8 warps.
// Warp grid: 2(M) x 4(N); warp tile m32 x n64 (one row segment of 64 px).
// K order: ic-chunks of 8 (outer), taps (inner-9) -> one k8-step per tap.
// Xs[8][4][134]: input rows y0-1..y0+2, cols -1..128 zero-padded, TF32.
//     ic stride 536 % 32 = 24 -> B-fragment LDS conflict-free.
// Ws[9][8][76]:  [tap][ic][oc], oc stride 76 % 32 = 12 -> A-frag conflict-free.
// ---------------------------------------------------------------------------
template <int CIN>
__global__ __launch_bounds__(256, 2) void conv3x3_mma(
    const float* __restrict__ in, const float* __restrict__ w,
    const float* __restrict__ bb, const float* __restrict__ gg,
    const float* __restrict__ be, const float* __restrict__ mm,
    const float* __restrict__ vv, float* __restrict__ out,
    int outCstride, int outCoff) {
    __shared__ uint32_t Xs[8][4][134];   // 17,152 B
    __shared__ uint32_t Ws[9][8][76];    // 21,888 B

    const int y0 = blockIdx.x * 2;
    const int ocBase = blockIdx.y * 64;
    const int b = blockIdx.z;
    const int tid = threadIdx.x;
    const int lane = tid & 31;
    const int warp = tid >> 5;

    const int wm = warp >> 2;        // 0..1 : oc 32-block
    const int wn = warp & 3;         // 0..3
    const int row_sel = wn >> 1;     // which of the 2 output rows
    const int px0 = (wn & 1) * 64;   // 64-px segment within the row

    const int tig = lane & 3;        // thread-in-group
    const int grp = lane >> 2;       // group id

    float acc[2][8][4];
    #pragma unroll
    for (int mf = 0; mf < 2; mf++)
        #pragma unroll
        for (int nf = 0; nf < 8; nf++)
            #pragma unroll
            for (int r = 0; r < 4; r++) acc[mf][nf][r] = 0.f;

    const float* inb = in + (size_t)b * CIN * HWSZ;

    const uint32_t* pB = &Xs[tig][row_sel][px0 + grp];
    const uint32_t* pA = &Ws[0][tig][wm * 32 + grp];

    for (int cc = 0; cc < CIN / 8; ++cc) {
        __syncthreads();
        // ---- load input tile: 8 ic x 4 rows x 130 cols (zero-padded) ----
        {
            const float* src = inb + (size_t)(cc * 8) * HWSZ;
            for (int i = tid; i < 8 * 4 * 130; i += 256) {
                int ic = i / 520;
                int r = i - ic * 520;
                int yy = r / 130;
                int xx = r - yy * 130;
                int gy = y0 - 1 + yy;
                int gx = xx - 1;
                float v = 0.f;
                if ((unsigned)gy < (unsigned)HH && (unsigned)gx < (unsigned)WW)
                    v = src[(size_t)ic * HWSZ + gy * WW + gx];
                Xs[ic][yy][xx] = f2tf32(v);
            }
        }
        // ---- load weights: 64 oc x 8 ic x 9 taps (contiguous 72/oc) ----
        {
            const float* wsrc = w + ((size_t)ocBase * CIN + (size_t)cc * 8) * 9;
            for (int i = tid; i < 64 * 72; i += 256) {
                int oc = i / 72;
                int r = i - oc * 72;
                int ic = r / 9;
                int tap = r - ic * 9;
                float v = wsrc[(size_t)oc * CIN * 9 + r];
                Ws[tap][ic][oc] = f2tf32(v);
            }
        }
        __syncthreads();

        // ---- 9 k8-steps (one per tap, k = 8 input channels) ----
        #pragma unroll
        for (int tap = 0; tap < 9; ++tap) {
            const int ky = tap / 3;
            const int kx = tap - ky * 3;

            uint32_t a[2][4];
            #pragma unroll
            for (int mf = 0; mf < 2; mf++) {
                const int base = tap * (8 * 76) + mf * 16;
                a[mf][0] = pA[base];
                a[mf][1] = pA[base + 8];
                a[mf][2] = pA[base + 4 * 76];
                a[mf][3] = pA[base + 4 * 76 + 8];
            }
            #pragma unroll
            for (int nf = 0; nf < 8; nf++) {
                const int boff = ky * 134 + kx + nf * 8;
                uint32_t b0 = pB[boff];
                uint32_t b1 = pB[boff + 4 * 536];
                mma_tf32(acc[0][nf], a[0], b0, b1);
                mma_tf32(acc[1][nf], a[1], b0, b1);
            }
        }
    }

    // ---- epilogue: BN + ReLU, float2 stores ----
    const int y_out = y0 + row_sel;
    #pragma unroll
    for (int mf = 0; mf < 2; mf++) {
        #pragma unroll
        for (int rr = 0; rr < 2; rr++) {
            int oc = ocBase + wm * 32 + mf * 16 + grp + rr * 8;
            float s = __ldg(&gg[oc]) * rsqrtf(__ldg(&vv[oc]) + EPSV);
            float t = (__ldg(&bb[oc]) - __ldg(&mm[oc])) * s + __ldg(&be[oc]);
            float* op = out +
                        ((size_t)(b * outCstride + outCoff + oc)) * HWSZ +
                        y_out * WW + px0 + tig * 2;
            #pragma unroll
            for (int nf = 0; nf < 8; nf++) {
                float2 v;
                v.x = fmaxf(fmaf(acc[mf][nf][rr * 2 + 0], s, t), 0.f);
                v.y = fmaxf(fmaf(acc[mf][nf][rr * 2 + 1], s, t), 0.f);
                *(float2*)(op + nf * 8) = v;
            }
        }
    }
}

// ---------------------------------------------------------------------------
// Kernel 3: sobel depthwise (summed kernel), pad=1. Memory bound.
// ---------------------------------------------------------------------------
__global__ __launch_bounds__(256) void sobel_dw(const float* __restrict__ in,
                                                float* __restrict__ out,
                                                int total) {
    int idx = blockIdx.x * 256 + threadIdx.x;
    if (idx >= total) return;
    int xw = idx & (WW - 1);
    int yh = (idx >> 7) & (HH - 1);
    const float* p = in + idx;
    bool up = yh > 0, dn = yh < HH - 1, lf = xw > 0, rt = xw < WW - 1;
    float s = 0.f;
    if (up) {
        if (lf) s = fmaf(2.f, p[-WW - 1], s);
        s = fmaf(4.f, p[-WW], s);
        if (rt) s = fmaf(4.f, p[-WW + 1], s);
    }
    if (lf) s = fmaf(-2.f, p[-1], s);
    if (rt) s = fmaf(2.f, p[1], s);
    if (dn) {
        if (lf) s = fmaf(-4.f, p[WW - 1], s);
        s = fmaf(-4.f, p[WW], s);
        if (rt) s = fmaf(-2.f, p[WW + 1], s);
    }
    out[idx] = s;
}

// ---------------------------------------------------------------------------
// Kernel 5: concat copy — out[:, 0:64] = input.
// ---------------------------------------------------------------------------
__global__ __launch_bounds__(256) void concat_copy(const float4* __restrict__ in,
                                                   float4* __restrict__ out) {
    int idx = blockIdx.x * 256 + threadIdx.x;
    int b = idx >> 18;
    int r = idx & 262143;
    out[(size_t)b * 524288 + r] = in[(size_t)b * 262144 + r];
}

// ---------------------------------------------------------------------------
extern "C" void kernel_launch(void* const* d_in, const int* in_sizes, int n_in,
                              void* d_out, int out_size) {
    const float* input = (const float*)d_in[0];
    const float* w1 = (const float*)d_in[1];
    const float* b1 = (const float*)d_in[2];
    const float* g1 = (const float*)d_in[3];
    const float* be1 = (const float*)d_in[4];
    const float* m1 = (const float*)d_in[5];
    const float* v1 = (const float*)d_in[6];
    const float* w2 = (const float*)d_in[7];
    const float* b2 = (const float*)d_in[8];
    const float* g2 = (const float*)d_in[9];
    const float* be2 = (const float*)d_in[10];
    const float* m2 = (const float*)d_in[11];
    const float* v2 = (const float*)d_in[12];
    const float* w3 = (const float*)d_in[13];
    const float* b3 = (const float*)d_in[14];
    const float* g3 = (const float*)d_in[15];
    const float* be3 = (const float*)d_in[16];
    const float* m3 = (const float*)d_in[17];
    const float* v3 = (const float*)d_in[18];
    float* out = (float*)d_out;

    float *c1, *c2, *edge;
    cudaGetSymbolAddress((void**)&c1, g_c1);
    cudaGetSymbolAddress((void**)&c2, g_c2);
    cudaGetSymbolAddress((void**)&edge, g_edge);

    // conv1: 1x1, 64->256, BN+ReLU (fp32)
    conv1x1_bn_relu<<<dim3(HWSZ / 64, C1 / 64, BATCH), 256>>>(
        input, w1, b1, g1, be1, m1, v1, c1);

    // conv2: 3x3, 256->128, BN+ReLU (TF32 tensor)
    conv3x3_mma<C1><<<dim3(HH / 2, C2 / 64, BATCH), 256>>>(
        c1, w2, b2, g2, be2, m2, v2, c2, C2, 0);

    // sobel depthwise
    {
        int total = BATCH * C2 * HWSZ;
        sobel_dw<<<(total + 255) / 256, 256>>>(c2, edge, total);
    }

    // conv3: 3x3, 128->64, BN+ReLU (TF32 tensor) -> out channels [64,128)
    conv3x3_mma<C2><<<dim3(HH / 2, C3 / 64, BATCH), 256>>>(
        edge, w3, b3, g3, be3, m3, v3, out, 128, 64);

    // concat: out channels [0,64) = input
    concat_copy<<<BATCH * (C_IN * HWSZ / 4) / 256, 256>>>(
        (const float4*)input, (float4*)out);
}

// round 3
// speedup vs baseline: 3.2121x; 1.6733x over previous
#include <cuda_runtime.h>
#include <cstdint>

// ---------------------------------------------------------------------------
//   input:  [16, 64, 128, 128]  fp32
//   conv1:  1x1, 64 -> 256, BN+ReLU  (TF32 mma)      -> c1 (tf32-rounded)
//   conv2:  3x3 pad1, 256 -> 128, BN+ReLU (TF32 mma) -> c2 (fp32)
//   sobel:  depthwise 3x3 pad1 (summed kernel)       -> edge (tf32-rounded)
//   conv3:  3x3 pad1, 128 -> 64, BN+ReLU (TF32 mma)  -> out[:,64:128]
//   concat: out[:,0:64] = input
// ---------------------------------------------------------------------------

#define BATCH 16
#define HH 128
#define WWID 128
#define HWSZ (HH * WWID)
#define C_IN 64
#define C1 256
#define C2 128
#define C3 64
#define EPSV 1e-5f

__device__ float g_c1[(size_t)BATCH * C1 * HWSZ];
__device__ float g_c2[(size_t)BATCH * C2 * HWSZ];
__device__ float g_edge[(size_t)BATCH * C2 * HWSZ];

// Pre-converted weight slabs (tf32 bits), laid out exactly as the smem tiles:
// 3x3: [ocb][cc][tap*8+ic][oc64];  1x1: [ocb][cc][ic][oc64]
__device__ uint32_t g_w2t[2 * 32 * 72 * 64];
__device__ uint32_t g_w3t[1 * 16 * 72 * 64];
__device__ uint32_t g_w1t[4 * 8 * 8 * 64];

// ---------------------------------------------------------------------------
// helpers
// ---------------------------------------------------------------------------
__device__ __forceinline__ uint32_t f2tf32(float x) {
    uint32_t r;
    asm("cvt.rna.tf32.f32 %0, %1;" : "=r"(r) : "f"(x));
    return r;
}
__device__ __forceinline__ uint32_t tf32_of_bits(uint32_t b) {
    return f2tf32(__uint_as_float(b));
}

__device__ __forceinline__ void mma_tf32(float c[4], const uint32_t a[4],
                                         uint32_t b0, uint32_t b1) {
    asm volatile(
        "mma.sync.aligned.m16n8k8.row.col.f32.tf32.tf32.f32 "
        "{%0,%1,%2,%3}, {%4,%5,%6,%7}, {%8,%9}, {%0,%1,%2,%3};"
        : "+f"(c[0]), "+f"(c[1]), "+f"(c[2]), "+f"(c[3])
        : "r"(a[0]), "r"(a[1]), "r"(a[2]), "r"(a[3]), "r"(b0), "r"(b1));
}

__device__ __forceinline__ void cp_async4(uint32_t dst, const void* src) {
    asm volatile("cp.async.ca.shared.global [%0], [%1], 4;\n" ::"r"(dst),
                 "l"(src));
}
__device__ __forceinline__ void cp_async16(uint32_t dst, const void* src) {
    asm volatile("cp.async.cg.shared.global [%0], [%1], 16;\n" ::"r"(dst),
                 "l"(src));
}
__device__ __forceinline__ void cp_commit() {
    asm volatile("cp.async.commit_group;\n" ::: "memory");
}
__device__ __forceinline__ void cp_wait1() {
    asm volatile("cp.async.wait_group 1;\n" ::: "memory");
}
__device__ __forceinline__ void cp_wait0() {
    asm volatile("cp.async.wait_group 0;\n" ::: "memory");
}

// ---------------------------------------------------------------------------
// weight prep kernels: fp32 [oc][ic][taps] -> tf32 slab
// ---------------------------------------------------------------------------
__global__ void prep_w3x3(const float* __restrict__ w, uint32_t* __restrict__ o,
                          int OC, int CIN) {
    int t = blockIdx.x * 256 + threadIdx.x;
    int total = OC * CIN * 9;
    if (t >= total) return;
    int oc = t / (CIN * 9);
    int r = t - oc * (CIN * 9);
    int ic = r / 9;
    int tap = r - ic * 9;
    int ocb = oc >> 6, oc64 = oc & 63;
    int cc = ic >> 3, icr = ic & 7;
    int NC = CIN / 8;
    o[(((size_t)ocb * NC + cc) * 72 + tap * 8 + icr) * 64 + oc64] = f2tf32(w[t]);
}

__global__ void prep_w1x1(const float* __restrict__ w, uint32_t* __restrict__ o) {
    int t = blockIdx.x * 256 + threadIdx.x;   // 256*64
    if (t >= C1 * C_IN) return;
    int oc = t / C_IN;
    int ic = t - oc * C_IN;
    int ocb = oc >> 6, oc64 = oc & 63;
    int cc = ic >> 3, icr = ic & 7;
    o[(((size_t)ocb * 8 + cc) * 8 + icr) * 64 + oc64] = f2tf32(w[t]);
}

// ---------------------------------------------------------------------------
// conv 3x3 + BN + ReLU, TF32 mma, cp.async double-buffered.
// CTA: 64 oc x 256 px (2 rows), 8 warps, warp m32 x n64.
// Xs stride 134 (tig*536%32=tig*24 -> B conflict-free)
// Ws stride 72  (tig*72 %32=tig*8  -> A conflict-free)
// ---------------------------------------------------------------------------
#define X_BUF_W 4288   // 8*4*134 words
#define W_BUF_W 5184   // 72*72 words
#define SMEM3X3_BYTES ((2 * X_BUF_W + 2 * W_BUF_W) * 4)

template <int CIN, bool ROUND_OUT>
__global__ __launch_bounds__(256, 2) void conv3x3_mma_pipe(
    const float* __restrict__ in, const uint32_t* __restrict__ wslab,
    const float* __restrict__ bb, const float* __restrict__ gg,
    const float* __restrict__ be, const float* __restrict__ mm,
    const float* __restrict__ vv, float* __restrict__ out, int outCstride,
    int outCoff) {
    constexpr int NC = CIN / 8;
    extern __shared__ uint32_t dsm[];
    uint32_t* Xb[2] = {dsm, dsm + X_BUF_W};
    uint32_t* Wb[2] = {dsm + 2 * X_BUF_W, dsm + 2 * X_BUF_W + W_BUF_W};
    const uint32_t smem_u32 =
        (uint32_t)__cvta_generic_to_shared((void*)dsm);

    const int y0 = blockIdx.x * 2;
    const int ocb = blockIdx.y;
    const int ocBase = ocb * 64;
    const int b = blockIdx.z;
    const int tid = threadIdx.x;
    const int lane = tid & 31;
    const int warp = tid >> 5;

    const int wm = warp >> 2;
    const int wn = warp & 3;
    const int row_sel = wn >> 1;
    const int px0 = (wn & 1) * 64;
    const int tig = lane & 3;
    const int grp = lane >> 2;

    const float* inb = in + (size_t)b * CIN * HWSZ;
    const uint32_t* ws_base = wslab + (size_t)ocb * NC * (72 * 64);

    // zero X buffers once (covers halo/padding cells that are never staged)
    for (int i = tid; i < 2 * X_BUF_W; i += 256) dsm[i] = 0;

    float acc[2][8][4];
    #pragma unroll
    for (int mf = 0; mf < 2; mf++)
        #pragma unroll
        for (int nf = 0; nf < 8; nf++)
            #pragma unroll
            for (int r = 0; r < 4; r++) acc[mf][nf][r] = 0.f;

    // ---- staging lambdas ----
    auto stage = [&](int buf, int cc) {
        // X: 8 ic x 4 rows x 128 valid cols, 4B cp.async
        const uint32_t xdst0 = smem_u32 + (buf ? X_BUF_W * 4 : 0);
        const float* src = inb + (size_t)(cc * 8) * HWSZ;
        #pragma unroll
        for (int i = tid; i < 8 * 4 * 128; i += 256) {
            int ic = i >> 9;
            int r = i & 511;
            int yy = r >> 7;
            int xx = r & 127;
            int gy = y0 - 1 + yy;
            if ((unsigned)gy < (unsigned)HH) {
                cp_async4(xdst0 + (((ic * 4 + yy) * 134) + xx + 1) * 4,
                          src + (size_t)ic * HWSZ + gy * WWID + xx);
            }
        }
        // W: contiguous slab -> 72 rows of 64 words, stride 72, 16B cp.async
        const uint32_t wdst0 =
            smem_u32 + (2 * X_BUF_W + (buf ? W_BUF_W : 0)) * 4;
        const uint32_t* ws = ws_base + (size_t)cc * (72 * 64);
        #pragma unroll
        for (int i = tid; i < 72 * 16; i += 256) {
            int row = i >> 4;
            int piece = i & 15;
            cp_async16(wdst0 + (row * 72 + piece * 4) * 4,
                       ws + row * 64 + piece * 4);
        }
    };

    auto compute = [&](int buf) {
        const uint32_t* pB = Xb[buf] + tig * 536 + row_sel * 134 + px0 + grp;
        const uint32_t* pA = Wb[buf] + tig * 72 + wm * 32 + grp;
        #pragma unroll
        for (int tap = 0; tap < 9; ++tap) {
            const int ky = tap / 3;
            const int kx = tap - ky * 3;
            uint32_t a[2][4];
            #pragma unroll
            for (int mf = 0; mf < 2; mf++) {
                const int base = tap * 576 + mf * 16;
                a[mf][0] = pA[base];
                a[mf][1] = pA[base + 8];
                a[mf][2] = pA[base + 288];
                a[mf][3] = pA[base + 296];
            }
            #pragma unroll
            for (int nf = 0; nf < 8; nf++) {
                const int boff = ky * 134 + kx + nf * 8;
                uint32_t b0 = pB[boff];
                uint32_t b1 = pB[boff + 2144];  // +4*536
                mma_tf32(acc[0][nf], a[0], b0, b1);
                mma_tf32(acc[1][nf], a[1], b0, b1);
            }
        }
    };

    // ---- pipelined mainloop ----
    stage(0, 0);
    cp_commit();
    int buf = 0;
    for (int cc = 0; cc < NC; ++cc) {
        if (cc + 1 < NC) stage(buf ^ 1, cc + 1);
        cp_commit();
        if (cc + 1 < NC) cp_wait1(); else cp_wait0();
        __syncthreads();
        compute(buf);
        __syncthreads();
        buf ^= 1;
    }

    // ---- epilogue: BN + ReLU (+ optional tf32 rounding) ----
    const int y_out = y0 + row_sel;
    #pragma unroll
    for (int mf = 0; mf < 2; mf++) {
        #pragma unroll
        for (int rr = 0; rr < 2; rr++) {
            int oc = ocBase + wm * 32 + mf * 16 + grp + rr * 8;
            float s = __ldg(&gg[oc]) * rsqrtf(__ldg(&vv[oc]) + EPSV);
            float t = (__ldg(&bb[oc]) - __ldg(&mm[oc])) * s + __ldg(&be[oc]);
            float* op = out + ((size_t)(b * outCstride + outCoff + oc)) * HWSZ +
                        y_out * WWID + px0 + tig * 2;
            #pragma unroll
            for (int nf = 0; nf < 8; nf++) {
                float2 v;
                v.x = fmaxf(fmaf(acc[mf][nf][rr * 2 + 0], s, t), 0.f);
                v.y = fmaxf(fmaf(acc[mf][nf][rr * 2 + 1], s, t), 0.f);
                if (ROUND_OUT) {
                    v.x = __uint_as_float(f2tf32(v.x));
                    v.y = __uint_as_float(f2tf32(v.y));
                }
                *(float2*)(op + nf * 8) = v;
            }
        }
    }
}

// ---------------------------------------------------------------------------
// conv 1x1 + BN + ReLU, TF32 mma, cp.async double-buffered.
// CTA: 64 oc x 256 px, 8 warps, warp m32 x n64. K = 64 in chunks of 8.
// Xs stride 264 (tig*264%32=tig*8 -> conflict-free); raw fp32 -> cvt at LDS.
// Output written tf32-rounded (feeds conv2).
// ---------------------------------------------------------------------------
#define X1_BUF_W 2112  // 8*264
#define W1_BUF_W 576   // 8*72
#define SMEM1X1_BYTES ((2 * X1_BUF_W + 2 * W1_BUF_W) * 4)

__global__ __launch_bounds__(256, 2) void conv1x1_mma_pipe(
    const float* __restrict__ x, const uint32_t* __restrict__ wslab,
    const float* __restrict__ bb, const float* __restrict__ gg,
    const float* __restrict__ be, const float* __restrict__ mm,
    const float* __restrict__ vv, float* __restrict__ out) {
    constexpr int NC = 8;
    extern __shared__ uint32_t dsm[];
    uint32_t* Xb[2] = {dsm, dsm + X1_BUF_W};
    uint32_t* Wb[2] = {dsm + 2 * X1_BUF_W, dsm + 2 * X1_BUF_W + W1_BUF_W};
    const uint32_t smem_u32 = (uint32_t)__cvta_generic_to_shared((void*)dsm);

    const int pxBase = blockIdx.x * 256;
    const int ocb = blockIdx.y;
    const int b = blockIdx.z;
    const int tid = threadIdx.x;
    const int lane = tid & 31;
    const int warp = tid >> 5;

    const int wm = warp >> 2;
    const int wn = warp & 3;
    const int px0 = wn * 64;
    const int tig = lane & 3;
    const int grp = lane >> 2;

    const float* xb = x + (size_t)b * C_IN * HWSZ + pxBase;
    const uint32_t* ws_base = wslab + (size_t)ocb * NC * (8 * 64);

    float acc[2][8][4];
    #pragma unroll
    for (int mf = 0; mf < 2; mf++)
        #pragma unroll
        for (int nf = 0; nf < 8; nf++)
            #pragma unroll
            for (int r = 0; r < 4; r++) acc[mf][nf][r] = 0.f;

    auto stage = [&](int buf, int cc) {
        const uint32_t xdst0 = smem_u32 + (buf ? X1_BUF_W * 4 : 0);
        const float* src = xb + (size_t)(cc * 8) * HWSZ;
        #pragma unroll
        for (int i = tid; i < 8 * 64; i += 256) {  // 512 x 16B = 8ic x 256px
            int ic = i >> 6;
            int piece = i & 63;
            cp_async16(xdst0 + (ic * 264 + piece * 4) * 4,
                       src + (size_t)ic * HWSZ + piece * 4);
        }
        const uint32_t wdst0 =
            smem_u32 + (2 * X1_BUF_W + (buf ? W1_BUF_W : 0)) * 4;
        const uint32_t* ws = ws_base + (size_t)cc * (8 * 64);
        if (tid < 128) {
            int row = tid >> 4;
            int piece = tid & 15;
            cp_async16(wdst0 + (row * 72 + piece * 4) * 4,
                       ws + row * 64 + piece * 4);
        }
    };

    auto compute = [&](int buf) {
        const uint32_t* pB = Xb[buf] + tig * 264 + px0 + grp;
        const uint32_t* pA = Wb[buf] + tig * 72 + wm * 32 + grp;
        uint32_t a[2][4];
        #pragma unroll
        for (int mf = 0; mf < 2; mf++) {
            const int base = mf * 16;
            a[mf][0] = pA[base];
            a[mf][1] = pA[base + 8];
            a[mf][2] = pA[base + 288];
            a[mf][3] = pA[base + 296];
        }
        #pragma unroll
        for (int nf = 0; nf < 8; nf++) {
            uint32_t b0 = tf32_of_bits(pB[nf * 8]);
            uint32_t b1 = tf32_of_bits(pB[1056 + nf * 8]);  // +4*264
            mma_tf32(acc[0][nf], a[0], b0, b1);
            mma_tf32(acc[1][nf], a[1], b0, b1);
        }
    };

    stage(0, 0);
    cp_commit();
    int buf = 0;
    for (int cc = 0; cc < NC; ++cc) {
        if (cc + 1 < NC) stage(buf ^ 1, cc + 1);
        cp_commit();
        if (cc + 1 < NC) cp_wait1(); else cp_wait0();
        __syncthreads();
        compute(buf);
        __syncthreads();
        buf ^= 1;
    }

    #pragma unroll
    for (int mf = 0; mf < 2; mf++) {
        #pragma unroll
        for (int rr = 0; rr < 2; rr++) {
            int oc = ocb * 64 + wm * 32 + mf * 16 + grp + rr * 8;
            float s = __ldg(&gg[oc]) * rsqrtf(__ldg(&vv[oc]) + EPSV);
            float t = (__ldg(&bb[oc]) - __ldg(&mm[oc])) * s + __ldg(&be[oc]);
            float* op = out + ((size_t)b * C1 + oc) * HWSZ + pxBase + px0 +
                        tig * 2;
            #pragma unroll
            for (int nf = 0; nf < 8; nf++) {
                float2 v;
                v.x = fmaxf(fmaf(acc[mf][nf][rr * 2 + 0], s, t), 0.f);
                v.y = fmaxf(fmaf(acc[mf][nf][rr * 2 + 1], s, t), 0.f);
                v.x = __uint_as_float(f2tf32(v.x));  // feeds conv2 (tf32)
                v.y = __uint_as_float(f2tf32(v.y));
                *(float2*)(op + nf * 8) = v;
            }
        }
    }
}

// ---------------------------------------------------------------------------
// sobel depthwise (summed kernel), pad=1; output tf32-rounded (feeds conv3)
// kernel (correlation): [[2,4,4],[-2,0,2],[-4,-4,-2]]
// ---------------------------------------------------------------------------
__global__ __launch_bounds__(256) void sobel_dw(const float* __restrict__ in,
                                                float* __restrict__ out,
                                                int total) {
    int idx = blockIdx.x * 256 + threadIdx.x;
    if (idx >= total) return;
    int xw = idx & (WWID - 1);
    int yh = (idx >> 7) & (HH - 1);
    const float* p = in + idx;
    bool up = yh > 0, dn = yh < HH - 1, lf = xw > 0, rt = xw < WWID - 1;
    float s = 0.f;
    if (up) {
        if (lf) s = fmaf(2.f, p[-WWID - 1], s);
        s = fmaf(4.f, p[-WWID], s);
        if (rt) s = fmaf(4.f, p[-WWID + 1], s);
    }
    if (lf) s = fmaf(-2.f, p[-1], s);
    if (rt) s = fmaf(2.f, p[1], s);
    if (dn) {
        if (lf) s = fmaf(-4.f, p[WWID - 1], s);
        s = fmaf(-4.f, p[WWID], s);
        if (rt) s = fmaf(-2.f, p[WWID + 1], s);
    }
    out[idx] = __uint_as_float(f2tf32(s));
}

__global__ __launch_bounds__(256) void concat_copy(const float4* __restrict__ in,
                                                   float4* __restrict__ out) {
    int idx = blockIdx.x * 256 + threadIdx.x;
    int b = idx >> 18;
    int r = idx & 262143;
    out[(size_t)b * 524288 + r] = in[(size_t)b * 262144 + r];
}

// ---------------------------------------------------------------------------
extern "C" void kernel_launch(void* const* d_in, const int* in_sizes, int n_in,
                              void* d_out, int out_size) {
    const float* input = (const float*)d_in[0];
    const float* w1 = (const float*)d_in[1];
    const float* b1 = (const float*)d_in[2];
    const float* g1 = (const float*)d_in[3];
    const float* be1 = (const float*)d_in[4];
    const float* m1 = (const float*)d_in[5];
    const float* v1 = (const float*)d_in[6];
    const float* w2 = (const float*)d_in[7];
    const float* b2 = (const float*)d_in[8];
    const float* g2 = (const float*)d_in[9];
    const float* be2 = (const float*)d_in[10];
    const float* m2 = (const float*)d_in[11];
    const float* v2 = (const float*)d_in[12];
    const float* w3 = (const float*)d_in[13];
    const float* b3 = (const float*)d_in[14];
    const float* g3 = (const float*)d_in[15];
    const float* be3 = (const float*)d_in[16];
    const float* m3 = (const float*)d_in[17];
    const float* v3 = (const float*)d_in[18];
    float* out = (float*)d_out;

    float *c1, *c2, *edge;
    cudaGetSymbolAddress((void**)&c1, g_c1);
    cudaGetSymbolAddress((void**)&c2, g_c2);
    cudaGetSymbolAddress((void**)&edge, g_edge);
    uint32_t *w1t, *w2t, *w3t;
    cudaGetSymbolAddress((void**)&w1t, g_w1t);
    cudaGetSymbolAddress((void**)&w2t, g_w2t);
    cudaGetSymbolAddress((void**)&w3t, g_w3t);

    static int attr_done = 0;
    if (!attr_done) {
        cudaFuncSetAttribute(conv3x3_mma_pipe<C1, false>,
                             cudaFuncAttributeMaxDynamicSharedMemorySize,
                             SMEM3X3_BYTES);
        cudaFuncSetAttribute(conv3x3_mma_pipe<C2, false>,
                             cudaFuncAttributeMaxDynamicSharedMemorySize,
                             SMEM3X3_BYTES);
        cudaFuncSetAttribute(conv1x1_mma_pipe,
                             cudaFuncAttributeMaxDynamicSharedMemorySize,
                             SMEM1X1_BYTES);
        attr_done = 1;
    }

    // weight prep (tf32 slabs)
    prep_w1x1<<<(C1 * C_IN + 255) / 256, 256>>>(w1, w1t);
    prep_w3x3<<<(C2 * C1 * 9 + 255) / 256, 256>>>(w2, w2t, C2, C1);
    prep_w3x3<<<(C3 * C2 * 9 + 255) / 256, 256>>>(w3, w3t, C3, C2);

    // conv1: 1x1, 64->256 (TF32), output tf32-rounded
    conv1x1_mma_pipe<<<dim3(HWSZ / 256, C1 / 64, BATCH), 256, SMEM1X1_BYTES>>>(
        input, w1t, b1, g1, be1, m1, v1, c1);

    // conv2: 3x3, 256->128 (TF32)
    conv3x3_mma_pipe<C1, false><<<dim3(HH / 2, C2 / 64, BATCH), 256,
                                  SMEM3X3_BYTES>>>(c1, w2t, b2, g2, be2, m2,
                                                   v2, c2, C2, 0);

    // sobel depthwise, output tf32-rounded
    {
        int total = BATCH * C2 * HWSZ;
        sobel_dw<<<(total + 255) / 256, 256>>>(c2, edge, total);
    }

    // conv3: 3x3, 128->64 (TF32) -> out channels [64,128)
    conv3x3_mma_pipe<C2, false><<<dim3(HH / 2, C3 / 64, BATCH), 256,
                                  SMEM3X3_BYTES>>>(edge, w3t, b3, g3, be3, m3,
                                                   v3, out, 128, 64);

    // concat: out channels [0,64) = input
    concat_copy<<<BATCH * (C_IN * HWSZ / 4) / 256, 256>>>(
        (const float4*)input, (float4*)out);
}

// round 8
// speedup vs baseline: 5.4517x; 1.6973x over previous
#include <cuda_runtime.h>
#include <cuda_fp16.h>
#include <cstdint>

// ---------------------------------------------------------------------------
//   input:  [16, 64, 128, 128]  fp32 NCHW
//   conv1:  1x1, 64 -> 256, BN+ReLU  (TF32 mma)       -> c1  NHWC fp16
//   conv2:  3x3 pad1, 256 -> 128, BN+ReLU (FP16 mma)  -> c2  NHWC fp32
//   sobel:  depthwise 3x3 pad1 (summed kernel)        -> edge NHWC fp16
//   conv3:  3x3 pad1, 128 -> 64, BN+ReLU (FP16 mma)   -> out[:,64:128] NCHW f32
//   concat: out[:,0:64] = input
//
// ROUND 7 FIX: __syncthreads() between smem halo zero-fill and the first
// cp.async stage. Without it, late zero-stores clobber landed cp.async data
// (races confirmed by run-to-run rel_err variance on identical source).
// ---------------------------------------------------------------------------

#define BATCH 16
#define HH 128
#define WWID 128
#define HWSZ (HH * WWID)
#define C_IN 64
#define C1 256
#define C2 128
#define C3 64
#define EPSV 1e-5f

__device__ __align__(16) __half g_c1h[(size_t)BATCH * HWSZ * C1];    // 128 MB
__device__ __align__(16) float g_c2f[(size_t)BATCH * HWSZ * C2];     // 128 MB
__device__ __align__(16) __half g_edgeh[(size_t)BATCH * HWSZ * C2];  // 64 MB
__device__ __align__(16) __half g_w2h[2 * 16 * 9 * 64 * 16];  // [ocb][cc][tap][oc64][ic16]
__device__ __align__(16) __half g_w3h[1 * 8 * 9 * 64 * 16];
__device__ uint32_t g_w1t[4 * 8 * 8 * 64];                    // conv1 tf32 slab

// ---------------------------------------------------------------------------
// helpers
// ---------------------------------------------------------------------------
__device__ __forceinline__ uint32_t f2tf32(float x) {
    uint32_t r;
    asm("cvt.rna.tf32.f32 %0, %1;" : "=r"(r) : "f"(x));
    return r;
}
__device__ __forceinline__ uint32_t tf32_of_bits(uint32_t b) {
    return f2tf32(__uint_as_float(b));
}

__device__ __forceinline__ void mma_tf32(float c[4], const uint32_t a[4],
                                         uint32_t b0, uint32_t b1) {
    asm volatile(
        "mma.sync.aligned.m16n8k8.row.col.f32.tf32.tf32.f32 "
        "{%0,%1,%2,%3}, {%4,%5,%6,%7}, {%8,%9}, {%0,%1,%2,%3};"
        : "+f"(c[0]), "+f"(c[1]), "+f"(c[2]), "+f"(c[3])
        : "r"(a[0]), "r"(a[1]), "r"(a[2]), "r"(a[3]), "r"(b0), "r"(b1));
}

__device__ __forceinline__ void mma_f16(float c[4], const uint32_t a[4],
                                        uint32_t b0, uint32_t b1) {
    asm volatile(
        "mma.sync.aligned.m16n8k16.row.col.f32.f16.f16.f32 "
        "{%0,%1,%2,%3}, {%4,%5,%6,%7}, {%8,%9}, {%0,%1,%2,%3};"
        : "+f"(c[0]), "+f"(c[1]), "+f"(c[2]), "+f"(c[3])
        : "r"(a[0]), "r"(a[1]), "r"(a[2]), "r"(a[3]), "r"(b0), "r"(b1));
}

__device__ __forceinline__ void cp_async16(uint32_t dst, const void* src) {
    asm volatile("cp.async.cg.shared.global [%0], [%1], 16;\n" ::"r"(dst),
                 "l"(src));
}
__device__ __forceinline__ void cp_commit() {
    asm volatile("cp.async.commit_group;\n" ::: "memory");
}
__device__ __forceinline__ void cp_wait1() {
    asm volatile("cp.async.wait_group 1;\n" ::: "memory");
}
__device__ __forceinline__ void cp_wait0() {
    asm volatile("cp.async.wait_group 0;\n" ::: "memory");
}

// ---------------------------------------------------------------------------
// weight prep
// ---------------------------------------------------------------------------
__global__ void prep_w3x3_h(const float* __restrict__ w,
                            __half* __restrict__ o, int OC, int CIN) {
    int t = blockIdx.x * 256 + threadIdx.x;
    int total = OC * CIN * 9;
    if (t >= total) return;
    int oc = t / (CIN * 9);
    int r = t - oc * (CIN * 9);
    int ic = r / 9;
    int tap = r - ic * 9;
    int ocb = oc >> 6, oc64 = oc & 63;
    int cc = ic >> 4, icr = ic & 15;
    int NC = CIN / 16;
    o[((((size_t)ocb * NC + cc) * 9 + tap) * 64 + oc64) * 16 + icr] =
        __float2half(w[t]);
}

__global__ void prep_w1x1(const float* __restrict__ w,
                          uint32_t* __restrict__ o) {
    int t = blockIdx.x * 256 + threadIdx.x;
    if (t >= C1 * C_IN) return;
    int oc = t / C_IN;
    int ic = t - oc * C_IN;
    int ocb = oc >> 6, oc64 = oc & 63;
    int cc = ic >> 3, icr = ic & 7;
    o[(((size_t)ocb * 8 + cc) * 8 + icr) * 64 + oc64] = f2tf32(w[t]);
}

// ---------------------------------------------------------------------------
// conv1: 1x1 64->256, TF32 mma, cp.async pipelined -> NHWC fp16
// (no zero-fill race here: every smem word is cp.async-written each chunk)
// ---------------------------------------------------------------------------
#define X1_BUF_W 2112  // 8*264
#define W1_BUF_W 576   // 8*72
#define SMEM1X1_BYTES ((2 * X1_BUF_W + 2 * W1_BUF_W) * 4)

__global__ __launch_bounds__(256, 2) void conv1x1_mma_pipe(
    const float* __restrict__ x, const uint32_t* __restrict__ wslab,
    const float* __restrict__ bb, const float* __restrict__ gg,
    const float* __restrict__ be, const float* __restrict__ mm,
    const float* __restrict__ vv, __half* __restrict__ out) {
    constexpr int NC = 8;
    extern __shared__ uint32_t dsm[];
    uint32_t* Xb[2] = {dsm, dsm + X1_BUF_W};
    uint32_t* Wb[2] = {dsm + 2 * X1_BUF_W, dsm + 2 * X1_BUF_W + W1_BUF_W};
    const uint32_t smem_u32 = (uint32_t)__cvta_generic_to_shared((void*)dsm);

    const int pxBase = blockIdx.x * 256;
    const int ocb = blockIdx.y;
    const int b = blockIdx.z;
    const int tid = threadIdx.x;
    const int lane = tid & 31;
    const int warp = tid >> 5;

    const int wm = warp >> 2;
    const int wn = warp & 3;
    const int px0 = wn * 64;
    const int tig = lane & 3;
    const int grp = lane >> 2;

    const float* xb = x + (size_t)b * C_IN * HWSZ + pxBase;
    const uint32_t* ws_base = wslab + (size_t)ocb * NC * (8 * 64);

    float acc[2][8][4];
    #pragma unroll
    for (int mf = 0; mf < 2; mf++)
        #pragma unroll
        for (int nf = 0; nf < 8; nf++)
            #pragma unroll
            for (int r = 0; r < 4; r++) acc[mf][nf][r] = 0.f;

    auto stage = [&](int buf, int cc) {
        const uint32_t xdst0 = smem_u32 + (buf ? X1_BUF_W * 4 : 0);
        const float* src = xb + (size_t)(cc * 8) * HWSZ;
        #pragma unroll
        for (int i = tid; i < 8 * 64; i += 256) {
            int ic = i >> 6;
            int piece = i & 63;
            cp_async16(xdst0 + (ic * 264 + piece * 4) * 4,
                       src + (size_t)ic * HWSZ + piece * 4);
        }
        const uint32_t wdst0 =
            smem_u32 + (2 * X1_BUF_W + (buf ? W1_BUF_W : 0)) * 4;
        const uint32_t* ws = ws_base + (size_t)cc * (8 * 64);
        if (tid < 128) {
            int row = tid >> 4;
            int piece = tid & 15;
            cp_async16(wdst0 + (row * 72 + piece * 4) * 4,
                       ws + row * 64 + piece * 4);
        }
    };

    auto compute = [&](int buf) {
        const uint32_t* pB = Xb[buf] + tig * 264 + px0 + grp;
        const uint32_t* pA = Wb[buf] + tig * 72 + wm * 32 + grp;
        uint32_t a[2][4];
        #pragma unroll
        for (int mf = 0; mf < 2; mf++) {
            const int base = mf * 16;
            a[mf][0] = pA[base];
            a[mf][1] = pA[base + 8];
            a[mf][2] = pA[base + 288];
            a[mf][3] = pA[base + 296];
        }
        #pragma unroll
        for (int nf = 0; nf < 8; nf++) {
            uint32_t b0 = tf32_of_bits(pB[nf * 8]);
            uint32_t b1 = tf32_of_bits(pB[1056 + nf * 8]);
            mma_tf32(acc[0][nf], a[0], b0, b1);
            mma_tf32(acc[1][nf], a[1], b0, b1);
        }
    };

    stage(0, 0);
    cp_commit();
    int buf = 0;
    for (int cc = 0; cc < NC; ++cc) {
        if (cc + 1 < NC) stage(buf ^ 1, cc + 1);
        cp_commit();
        if (cc + 1 < NC) cp_wait1(); else cp_wait0();
        __syncthreads();
        compute(buf);
        __syncthreads();
        buf ^= 1;
    }

    // epilogue: BN + ReLU -> NHWC fp16
    #pragma unroll
    for (int mf = 0; mf < 2; mf++) {
        #pragma unroll
        for (int rr = 0; rr < 2; rr++) {
            int oc = ocb * 64 + wm * 32 + mf * 16 + grp + rr * 8;
            float s = __ldg(&gg[oc]) * rsqrtf(__ldg(&vv[oc]) + EPSV);
            float t = (__ldg(&bb[oc]) - __ldg(&mm[oc])) * s + __ldg(&be[oc]);
            #pragma unroll
            for (int nf = 0; nf < 8; nf++) {
                float v0 = fmaxf(fmaf(acc[mf][nf][rr * 2 + 0], s, t), 0.f);
                float v1 = fmaxf(fmaf(acc[mf][nf][rr * 2 + 1], s, t), 0.f);
                int pxl = pxBase + px0 + nf * 8 + tig * 2;
                __half* dst = out + ((size_t)b * HWSZ + pxl) * C1 + oc;
                dst[0] = __float2half(v0);
                dst[C1] = __float2half(v1);
            }
        }
    }
}

// ---------------------------------------------------------------------------
// conv3x3 fp16 implicit GEMM.  A = pixels (NHWC halves, cp.async), B = weights.
// CTA: 256 px (2 output rows) x 64 oc. 8 warps: warp = m32 x n64.
// MODE 0: out NHWC fp32 (C=128).  MODE 1: out NCHW fp32, ch offset 64.
// ---------------------------------------------------------------------------
#define XPXW 12
#define XROWW (130 * XPXW)
#define XBUFW (4 * XROWW)          // 6240
#define WBUFW (576 * XPXW)         // 6912
#define SMEMF16_WORDS (2 * XBUFW + 2 * WBUFW)
#define SMEMF16_BYTES (SMEMF16_WORDS * 4)

template <int CIN, int MODE>
__global__ __launch_bounds__(256, 2) void conv3x3_f16(
    const __half* __restrict__ in, const __half* __restrict__ wslab,
    const float* __restrict__ bb, const float* __restrict__ gg,
    const float* __restrict__ be, const float* __restrict__ mm,
    const float* __restrict__ vv, float* __restrict__ outp) {
    constexpr int NC = CIN / 16;
    extern __shared__ uint32_t dsm[];
    const uint32_t smem_u32 = (uint32_t)__cvta_generic_to_shared((void*)dsm);

    const int y0 = blockIdx.x * 2;
    const int ocb = blockIdx.y;
    const int b = blockIdx.z;
    const int tid = threadIdx.x;
    const int lane = tid & 31;
    const int warp = tid >> 5;
    const int row_out = warp >> 2;
    const int x0 = (warp & 3) * 32;
    const int grp = lane >> 2;
    const int tig = lane & 3;

    const __half* inb = in + (size_t)b * HWSZ * CIN;
    const __half* wsb = wslab + (size_t)ocb * ((size_t)NC * 9 * 64 * 16);

    // zero X halo regions once...
    for (int i = tid; i < 2 * XBUFW; i += 256) dsm[i] = 0;
    // ...and make ALL zero-stores visible before any cp.async can land.
    // (Without this barrier, late zero-stores clobber landed tile data.)
    __syncthreads();

    float acc[2][8][4];
    #pragma unroll
    for (int mf = 0; mf < 2; mf++)
        #pragma unroll
        for (int nf = 0; nf < 8; nf++)
            #pragma unroll
            for (int r = 0; r < 4; r++) acc[mf][nf][r] = 0.f;

    auto stage = [&](int buf, int cc) {
        const uint32_t xdst = smem_u32 + (buf ? XBUFW * 4 : 0);
        const __half* xs = inb + cc * 16;
        #pragma unroll
        for (int i = tid; i < 1024; i += 256) {
            int row = i >> 8;
            int r = i & 255;
            int px = r >> 1;
            int piece = r & 1;
            int gy = y0 - 1 + row;
            if ((unsigned)gy < (unsigned)HH)
                cp_async16(xdst + (((row * 130) + px + 1) * XPXW + piece * 4) * 4,
                           xs + ((size_t)gy * WWID + px) * CIN + piece * 8);
        }
        const uint32_t wdst = smem_u32 + (2 * XBUFW + (buf ? WBUFW : 0)) * 4;
        const __half* ws = wsb + (size_t)cc * (9 * 64 * 16);
        #pragma unroll
        for (int i = tid; i < 1152; i += 256) {
            int row = i >> 1;
            int piece = i & 1;
            cp_async16(wdst + (row * XPXW + piece * 4) * 4,
                       ws + row * 16 + piece * 8);
        }
    };

    auto compute = [&](int buf) {
        const uint32_t* X = dsm + (buf ? XBUFW : 0);
        const uint32_t* W = dsm + 2 * XBUFW + (buf ? WBUFW : 0);
        #pragma unroll
        for (int tap = 0; tap < 9; ++tap) {
            const int ky = tap / 3;
            const int kx = tap - ky * 3;
            const uint32_t* A =
                X + ((row_out + ky) * 130 + x0 + kx) * XPXW + tig;
            uint32_t a[2][4];
            #pragma unroll
            for (int mf = 0; mf < 2; mf++) {
                const int m0 = (mf * 16 + grp) * XPXW;
                a[mf][0] = A[m0];
                a[mf][1] = A[m0 + 8 * XPXW];
                a[mf][2] = A[m0 + 4];
                a[mf][3] = A[m0 + 8 * XPXW + 4];
            }
            const uint32_t* Bp = W + (tap * 64 + grp) * XPXW + tig;
            #pragma unroll
            for (int nf = 0; nf < 8; nf++) {
                uint32_t b0 = Bp[nf * 8 * XPXW];
                uint32_t b1 = Bp[nf * 8 * XPXW + 4];
                mma_f16(acc[0][nf], a[0], b0, b1);
                mma_f16(acc[1][nf], a[1], b0, b1);
            }
        }
    };

    stage(0, 0);
    cp_commit();
    int buf = 0;
    for (int cc = 0; cc < NC; ++cc) {
        if (cc + 1 < NC) stage(buf ^ 1, cc + 1);
        cp_commit();
        if (cc + 1 < NC) cp_wait1(); else cp_wait0();
        __syncthreads();
        compute(buf);
        __syncthreads();
        buf ^= 1;
    }

    if (MODE == 0) {
        // NHWC fp32 output (c2 stays full precision for sobel cancellation)
        float* out = outp + (size_t)b * HWSZ * C2;
        #pragma unroll
        for (int nf = 0; nf < 8; nf++) {
            int oc = ocb * 64 + nf * 8 + 2 * tig;
            float s0 = __ldg(&gg[oc]) * rsqrtf(__ldg(&vv[oc]) + EPSV);
            float t0 = (__ldg(&bb[oc]) - __ldg(&mm[oc])) * s0 + __ldg(&be[oc]);
            float s1 = __ldg(&gg[oc + 1]) * rsqrtf(__ldg(&vv[oc + 1]) + EPSV);
            float t1 = (__ldg(&bb[oc + 1]) - __ldg(&mm[oc + 1])) * s1 +
                       __ldg(&be[oc + 1]);
            #pragma unroll
            for (int mf = 0; mf < 2; mf++)
                #pragma unroll
                for (int h = 0; h < 2; h++) {
                    int px = (y0 + row_out) * WWID + x0 + mf * 16 + grp + h * 8;
                    float2 v;
                    v.x = fmaxf(fmaf(acc[mf][nf][h * 2 + 0], s0, t0), 0.f);
                    v.y = fmaxf(fmaf(acc[mf][nf][h * 2 + 1], s1, t1), 0.f);
                    *(float2*)(out + (size_t)px * C2 + oc) = v;
                }
        }
    } else {
        // NCHW fp32 output at channel offset 64, smem transpose for coalescing
        float* Csm = (float*)dsm;  // [256 px][stride 65]
        #pragma unroll
        for (int nf = 0; nf < 8; nf++) {
            int ocL = nf * 8 + 2 * tig;
            float s0 = __ldg(&gg[ocL]) * rsqrtf(__ldg(&vv[ocL]) + EPSV);
            float t0 =
                (__ldg(&bb[ocL]) - __ldg(&mm[ocL])) * s0 + __ldg(&be[ocL]);
            float s1 = __ldg(&gg[ocL + 1]) * rsqrtf(__ldg(&vv[ocL + 1]) + EPSV);
            float t1 = (__ldg(&bb[ocL + 1]) - __ldg(&mm[ocL + 1])) * s1 +
                       __ldg(&be[ocL + 1]);
            #pragma unroll
            for (int mf = 0; mf < 2; mf++)
                #pragma unroll
                for (int h = 0; h < 2; h++) {
                    int pxL = row_out * 128 + x0 + mf * 16 + grp + h * 8;
                    Csm[pxL * 65 + ocL] =
                        fmaxf(fmaf(acc[mf][nf][h * 2 + 0], s0, t0), 0.f);
                    Csm[pxL * 65 + ocL + 1] =
                        fmaxf(fmaf(acc[mf][nf][h * 2 + 1], s1, t1), 0.f);
                }
        }
        __syncthreads();
        #pragma unroll
        for (int i = 0; i < 8; i++) {
            int ocL = warp * 8 + i;
            float* op =
                outp + ((size_t)(b * 128 + 64 + ocL)) * HWSZ + y0 * WWID;
            #pragma unroll
            for (int c = 0; c < 8; c++) {
                int pxL = c * 32 + lane;
                op[pxL] = Csm[pxL * 65 + ocL];
            }
        }
    }
}

// ---------------------------------------------------------------------------
// sobel depthwise: NHWC fp32 in -> NHWC fp16 out (8 channels / thread)
// kernel (correlation): [[2,4,4],[-2,0,2],[-4,-4,-2]]
// ---------------------------------------------------------------------------
__global__ __launch_bounds__(256) void sobel_nhwc(const float* __restrict__ in,
                                                  __half* __restrict__ out) {
    int idx = blockIdx.x * 256 + threadIdx.x;  // B*HW*16 threads
    int cg = idx & 15;
    int x = (idx >> 4) & 127;
    int y = (idx >> 11) & 127;
    int b = idx >> 18;
    const float* base = in + ((size_t)b * HWSZ + y * WWID + x) * C2 + cg * 8;

    float acc[8];
    #pragma unroll
    for (int k = 0; k < 8; k++) acc[k] = 0.f;

    auto add = [&](int dy, int dx, float c) {
        int yy = y + dy, xx = x + dx;
        if ((unsigned)yy < (unsigned)HH && (unsigned)xx < (unsigned)WWID) {
            const float* p = base + (dy * WWID + dx) * C2;
            float4 v0 = *(const float4*)p;
            float4 v1 = *(const float4*)(p + 4);
            acc[0] = fmaf(c, v0.x, acc[0]);
            acc[1] = fmaf(c, v0.y, acc[1]);
            acc[2] = fmaf(c, v0.z, acc[2]);
            acc[3] = fmaf(c, v0.w, acc[3]);
            acc[4] = fmaf(c, v1.x, acc[4]);
            acc[5] = fmaf(c, v1.y, acc[5]);
            acc[6] = fmaf(c, v1.z, acc[6]);
            acc[7] = fmaf(c, v1.w, acc[7]);
        }
    };
    add(-1, -1, 2.f);  add(-1, 0, 4.f);  add(-1, 1, 4.f);
    add(0, -1, -2.f);                    add(0, 1, 2.f);
    add(1, -1, -4.f);  add(1, 0, -4.f);  add(1, 1, -2.f);

    __half2 r[4];
    #pragma unroll
    for (int k = 0; k < 4; k++)
        r[k] = __floats2half2_rn(acc[2 * k], acc[2 * k + 1]);
    *(uint4*)(out + ((size_t)b * HWSZ + y * WWID + x) * C2 + cg * 8) =
        *(uint4*)r;
}

// ---------------------------------------------------------------------------
__global__ __launch_bounds__(256) void concat_copy(const float4* __restrict__ in,
                                                   float4* __restrict__ out) {
    int idx = blockIdx.x * 256 + threadIdx.x;
    int b = idx >> 18;
    int r = idx & 262143;
    out[(size_t)b * 524288 + r] = in[(size_t)b * 262144 + r];
}

// ---------------------------------------------------------------------------
extern "C" void kernel_launch(void* const* d_in, const int* in_sizes, int n_in,
                              void* d_out, int out_size) {
    const float* input = (const float*)d_in[0];
    const float* w1 = (const float*)d_in[1];
    const float* b1 = (const float*)d_in[2];
    const float* g1 = (const float*)d_in[3];
    const float* be1 = (const float*)d_in[4];
    const float* m1 = (const float*)d_in[5];
    const float* v1 = (const float*)d_in[6];
    const float* w2 = (const float*)d_in[7];
    const float* b2 = (const float*)d_in[8];
    const float* g2 = (const float*)d_in[9];
    const float* be2 = (const float*)d_in[10];
    const float* m2 = (const float*)d_in[11];
    const float* v2 = (const float*)d_in[12];
    const float* w3 = (const float*)d_in[13];
    const float* b3 = (const float*)d_in[14];
    const float* g3 = (const float*)d_in[15];
    const float* be3 = (const float*)d_in[16];
    const float* m3 = (const float*)d_in[17];
    const float* v3 = (const float*)d_in[18];
    float* out = (float*)d_out;

    __half *c1h, *edgeh, *w2h, *w3h;
    float* c2f;
    uint32_t* w1t;
    cudaGetSymbolAddress((void**)&c1h, g_c1h);
    cudaGetSymbolAddress((void**)&c2f, g_c2f);
    cudaGetSymbolAddress((void**)&edgeh, g_edgeh);
    cudaGetSymbolAddress((void**)&w2h, g_w2h);
    cudaGetSymbolAddress((void**)&w3h, g_w3h);
    cudaGetSymbolAddress((void**)&w1t, g_w1t);

    static int attr_done = 0;
    if (!attr_done) {
        cudaFuncSetAttribute(conv1x1_mma_pipe,
                             cudaFuncAttributeMaxDynamicSharedMemorySize,
                             SMEM1X1_BYTES);
        cudaFuncSetAttribute(conv3x3_f16<C1, 0>,
                             cudaFuncAttributeMaxDynamicSharedMemorySize,
                             SMEMF16_BYTES);
        cudaFuncSetAttribute(conv3x3_f16<C2, 1>,
                             cudaFuncAttributeMaxDynamicSharedMemorySize,
                             SMEMF16_BYTES);
        attr_done = 1;
    }

    // weight prep
    prep_w1x1<<<(C1 * C_IN + 255) / 256, 256>>>(w1, w1t);
    prep_w3x3_h<<<(C2 * C1 * 9 + 255) / 256, 256>>>(w2, w2h, C2, C1);
    prep_w3x3_h<<<(C3 * C2 * 9 + 255) / 256, 256>>>(w3, w3h, C3, C2);

    // conv1: 1x1 64->256 (TF32) -> NHWC fp16
    conv1x1_mma_pipe<<<dim3(HWSZ / 256, C1 / 64, BATCH), 256, SMEM1X1_BYTES>>>(
        input, w1t, b1, g1, be1, m1, v1, c1h);

    // conv2: 3x3 256->128 (FP16 mma) -> NHWC fp32
    conv3x3_f16<C1, 0><<<dim3(HH / 2, 2, BATCH), 256, SMEMF16_BYTES>>>(
        c1h, w2h, b2, g2, be2, m2, v2, c2f);

    // sobel depthwise (fp32 in -> fp16 out)
    sobel_nhwc<<<BATCH * HWSZ * (C2 / 8) / 256, 256>>>(c2f, edgeh);

    // conv3: 3x3 128->64 (FP16 mma) -> out[:,64:128] NCHW fp32
    conv3x3_f16<C2, 1><<<dim3(HH / 2, 1, BATCH), 256, SMEMF16_BYTES>>>(
        edgeh, w3h, b3, g3, be3, m3, v3, out);

    // concat: out[:,0:64] = input
    concat_copy<<<BATCH * (C_IN * HWSZ / 4) / 256, 256>>>(
        (const float4*)input, (float4*)out);
}

// round 9
// speedup vs baseline: 5.8261x; 1.0687x over previous
#include <cuda_runtime.h>
#include <cuda_fp16.h>
#include <cstdint>

// ---------------------------------------------------------------------------
//   input:  [16, 64, 128, 128]  fp32 NCHW
//   conv1:  1x1, 64 -> 256, BN+ReLU  (TF32 mma)       -> c1  NHWC fp16
//   conv2:  3x3 pad1, 256 -> 128, BN+ReLU (FP16 mma)  -> c2  NHWC fp32
//   sobel:  depthwise 3x3 pad1 (summed kernel)        -> edge NHWC fp16
//   conv3:  3x3 pad1, 128 -> 64, BN+ReLU (FP16 mma)   -> out[:,64:128] NCHW f32
//   concat: out[:,0:64] = input
//
// R8 -> R9: conv3x3 fragment loads via ldmatrix.x4 (2 for A, 4 for B per tap)
// instead of 24 scalar LDS. Same fragments, bit-identical math.
// ---------------------------------------------------------------------------

#define BATCH 16
#define HH 128
#define WWID 128
#define HWSZ (HH * WWID)
#define C_IN 64
#define C1 256
#define C2 128
#define C3 64
#define EPSV 1e-5f

__device__ __align__(16) __half g_c1h[(size_t)BATCH * HWSZ * C1];    // 128 MB
__device__ __align__(16) float g_c2f[(size_t)BATCH * HWSZ * C2];     // 128 MB
__device__ __align__(16) __half g_edgeh[(size_t)BATCH * HWSZ * C2];  // 64 MB
__device__ __align__(16) __half g_w2h[2 * 16 * 9 * 64 * 16];  // [ocb][cc][tap][oc64][ic16]
__device__ __align__(16) __half g_w3h[1 * 8 * 9 * 64 * 16];
__device__ uint32_t g_w1t[4 * 8 * 8 * 64];                    // conv1 tf32 slab

// ---------------------------------------------------------------------------
// helpers
// ---------------------------------------------------------------------------
__device__ __forceinline__ uint32_t f2tf32(float x) {
    uint32_t r;
    asm("cvt.rna.tf32.f32 %0, %1;" : "=r"(r) : "f"(x));
    return r;
}
__device__ __forceinline__ uint32_t tf32_of_bits(uint32_t b) {
    return f2tf32(__uint_as_float(b));
}

__device__ __forceinline__ void mma_tf32(float c[4], const uint32_t a[4],
                                         uint32_t b0, uint32_t b1) {
    asm volatile(
        "mma.sync.aligned.m16n8k8.row.col.f32.tf32.tf32.f32 "
        "{%0,%1,%2,%3}, {%4,%5,%6,%7}, {%8,%9}, {%0,%1,%2,%3};"
        : "+f"(c[0]), "+f"(c[1]), "+f"(c[2]), "+f"(c[3])
        : "r"(a[0]), "r"(a[1]), "r"(a[2]), "r"(a[3]), "r"(b0), "r"(b1));
}

__device__ __forceinline__ void mma_f16(float c[4], const uint32_t a[4],
                                        uint32_t b0, uint32_t b1) {
    asm volatile(
        "mma.sync.aligned.m16n8k16.row.col.f32.f16.f16.f32 "
        "{%0,%1,%2,%3}, {%4,%5,%6,%7}, {%8,%9}, {%0,%1,%2,%3};"
        : "+f"(c[0]), "+f"(c[1]), "+f"(c[2]), "+f"(c[3])
        : "r"(a[0]), "r"(a[1]), "r"(a[2]), "r"(a[3]), "r"(b0), "r"(b1));
}

__device__ __forceinline__ void ldsm_x4(uint32_t r[4], uint32_t addr) {
    asm volatile(
        "ldmatrix.sync.aligned.m8n8.x4.shared.b16 {%0,%1,%2,%3}, [%4];"
        : "=r"(r[0]), "=r"(r[1]), "=r"(r[2]), "=r"(r[3])
        : "r"(addr));
}

__device__ __forceinline__ void cp_async16(uint32_t dst, const void* src) {
    asm volatile("cp.async.cg.shared.global [%0], [%1], 16;\n" ::"r"(dst),
                 "l"(src));
}
__device__ __forceinline__ void cp_commit() {
    asm volatile("cp.async.commit_group;\n" ::: "memory");
}
__device__ __forceinline__ void cp_wait1() {
    asm volatile("cp.async.wait_group 1;\n" ::: "memory");
}
__device__ __forceinline__ void cp_wait0() {
    asm volatile("cp.async.wait_group 0;\n" ::: "memory");
}

// ---------------------------------------------------------------------------
// weight prep
// ---------------------------------------------------------------------------
__global__ void prep_w3x3_h(const float* __restrict__ w,
                            __half* __restrict__ o, int OC, int CIN) {
    int t = blockIdx.x * 256 + threadIdx.x;
    int total = OC * CIN * 9;
    if (t >= total) return;
    int oc = t / (CIN * 9);
    int r = t - oc * (CIN * 9);
    int ic = r / 9;
    int tap = r - ic * 9;
    int ocb = oc >> 6, oc64 = oc & 63;
    int cc = ic >> 4, icr = ic & 15;
    int NC = CIN / 16;
    o[((((size_t)ocb * NC + cc) * 9 + tap) * 64 + oc64) * 16 + icr] =
        __float2half(w[t]);
}

__global__ void prep_w1x1(const float* __restrict__ w,
                          uint32_t* __restrict__ o) {
    int t = blockIdx.x * 256 + threadIdx.x;
    if (t >= C1 * C_IN) return;
    int oc = t / C_IN;
    int ic = t - oc * C_IN;
    int ocb = oc >> 6, oc64 = oc & 63;
    int cc = ic >> 3, icr = ic & 7;
    o[(((size_t)ocb * 8 + cc) * 8 + icr) * 64 + oc64] = f2tf32(w[t]);
}

// ---------------------------------------------------------------------------
// conv1: 1x1 64->256, TF32 mma, cp.async pipelined -> NHWC fp16
// ---------------------------------------------------------------------------
#define X1_BUF_W 2112  // 8*264
#define W1_BUF_W 576   // 8*72
#define SMEM1X1_BYTES ((2 * X1_BUF_W + 2 * W1_BUF_W) * 4)

__global__ __launch_bounds__(256, 2) void conv1x1_mma_pipe(
    const float* __restrict__ x, const uint32_t* __restrict__ wslab,
    const float* __restrict__ bb, const float* __restrict__ gg,
    const float* __restrict__ be, const float* __restrict__ mm,
    const float* __restrict__ vv, __half* __restrict__ out) {
    constexpr int NC = 8;
    extern __shared__ uint32_t dsm[];
    uint32_t* Xb[2] = {dsm, dsm + X1_BUF_W};
    uint32_t* Wb[2] = {dsm + 2 * X1_BUF_W, dsm + 2 * X1_BUF_W + W1_BUF_W};
    const uint32_t smem_u32 = (uint32_t)__cvta_generic_to_shared((void*)dsm);

    const int pxBase = blockIdx.x * 256;
    const int ocb = blockIdx.y;
    const int b = blockIdx.z;
    const int tid = threadIdx.x;
    const int lane = tid & 31;
    const int warp = tid >> 5;

    const int wm = warp >> 2;
    const int wn = warp & 3;
    const int px0 = wn * 64;
    const int tig = lane & 3;
    const int grp = lane >> 2;

    const float* xb = x + (size_t)b * C_IN * HWSZ + pxBase;
    const uint32_t* ws_base = wslab + (size_t)ocb * NC * (8 * 64);

    float acc[2][8][4];
    #pragma unroll
    for (int mf = 0; mf < 2; mf++)
        #pragma unroll
        for (int nf = 0; nf < 8; nf++)
            #pragma unroll
            for (int r = 0; r < 4; r++) acc[mf][nf][r] = 0.f;

    auto stage = [&](int buf, int cc) {
        const uint32_t xdst0 = smem_u32 + (buf ? X1_BUF_W * 4 : 0);
        const float* src = xb + (size_t)(cc * 8) * HWSZ;
        #pragma unroll
        for (int i = tid; i < 8 * 64; i += 256) {
            int ic = i >> 6;
            int piece = i & 63;
            cp_async16(xdst0 + (ic * 264 + piece * 4) * 4,
                       src + (size_t)ic * HWSZ + piece * 4);
        }
        const uint32_t wdst0 =
            smem_u32 + (2 * X1_BUF_W + (buf ? W1_BUF_W : 0)) * 4;
        const uint32_t* ws = ws_base + (size_t)cc * (8 * 64);
        if (tid < 128) {
            int row = tid >> 4;
            int piece = tid & 15;
            cp_async16(wdst0 + (row * 72 + piece * 4) * 4,
                       ws + row * 64 + piece * 4);
        }
    };

    auto compute = [&](int buf) {
        const uint32_t* pB = Xb[buf] + tig * 264 + px0 + grp;
        const uint32_t* pA = Wb[buf] + tig * 72 + wm * 32 + grp;
        uint32_t a[2][4];
        #pragma unroll
        for (int mf = 0; mf < 2; mf++) {
            const int base = mf * 16;
            a[mf][0] = pA[base];
            a[mf][1] = pA[base + 8];
            a[mf][2] = pA[base + 288];
            a[mf][3] = pA[base + 296];
        }
        #pragma unroll
        for (int nf = 0; nf < 8; nf++) {
            uint32_t b0 = tf32_of_bits(pB[nf * 8]);
            uint32_t b1 = tf32_of_bits(pB[1056 + nf * 8]);
            mma_tf32(acc[0][nf], a[0], b0, b1);
            mma_tf32(acc[1][nf], a[1], b0, b1);
        }
    };

    stage(0, 0);
    cp_commit();
    int buf = 0;
    for (int cc = 0; cc < NC; ++cc) {
        if (cc + 1 < NC) stage(buf ^ 1, cc + 1);
        cp_commit();
        if (cc + 1 < NC) cp_wait1(); else cp_wait0();
        __syncthreads();
        compute(buf);
        __syncthreads();
        buf ^= 1;
    }

    // epilogue: BN + ReLU -> NHWC fp16
    #pragma unroll
    for (int mf = 0; mf < 2; mf++) {
        #pragma unroll
        for (int rr = 0; rr < 2; rr++) {
            int oc = ocb * 64 + wm * 32 + mf * 16 + grp + rr * 8;
            float s = __ldg(&gg[oc]) * rsqrtf(__ldg(&vv[oc]) + EPSV);
            float t = (__ldg(&bb[oc]) - __ldg(&mm[oc])) * s + __ldg(&be[oc]);
            #pragma unroll
            for (int nf = 0; nf < 8; nf++) {
                float v0 = fmaxf(fmaf(acc[mf][nf][rr * 2 + 0], s, t), 0.f);
                float v1 = fmaxf(fmaf(acc[mf][nf][rr * 2 + 1], s, t), 0.f);
                int pxl = pxBase + px0 + nf * 8 + tig * 2;
                __half* dst = out + ((size_t)b * HWSZ + pxl) * C1 + oc;
                dst[0] = __float2half(v0);
                dst[C1] = __float2half(v1);
            }
        }
    }
}

// ---------------------------------------------------------------------------
// conv3x3 fp16 implicit GEMM, ldmatrix fragment loads.
// CTA: 256 px (2 output rows) x 64 oc. 8 warps: warp = m32 x n64.
// X smem: [4 rows][130 px][12 words]; W smem: [9 tap][64 oc][12 words].
// Row stride 48B -> ldmatrix phases hit all 32 banks (12k mod 32 distinct).
// MODE 0: out NHWC fp32 (C=128).  MODE 1: out NCHW fp32, ch offset 64.
// ---------------------------------------------------------------------------
#define XPXW 12
#define XROWW (130 * XPXW)
#define XBUFW (4 * XROWW)          // 6240
#define WBUFW (576 * XPXW)         // 6912
#define SMEMF16_WORDS (2 * XBUFW + 2 * WBUFW)
#define SMEMF16_BYTES (SMEMF16_WORDS * 4)

template <int CIN, int MODE>
__global__ __launch_bounds__(256, 2) void conv3x3_f16(
    const __half* __restrict__ in, const __half* __restrict__ wslab,
    const float* __restrict__ bb, const float* __restrict__ gg,
    const float* __restrict__ be, const float* __restrict__ mm,
    const float* __restrict__ vv, float* __restrict__ outp) {
    constexpr int NC = CIN / 16;
    extern __shared__ uint32_t dsm[];
    const uint32_t smem_u32 = (uint32_t)__cvta_generic_to_shared((void*)dsm);

    const int y0 = blockIdx.x * 2;
    const int ocb = blockIdx.y;
    const int b = blockIdx.z;
    const int tid = threadIdx.x;
    const int lane = tid & 31;
    const int warp = tid >> 5;
    const int row_out = warp >> 2;
    const int x0 = (warp & 3) * 32;
    const int grp = lane >> 2;
    const int tig = lane & 3;

    const __half* inb = in + (size_t)b * HWSZ * CIN;
    const __half* wsb = wslab + (size_t)ocb * ((size_t)NC * 9 * 64 * 16);

    // zero X halo regions once, then barrier before any cp.async can land
    for (int i = tid; i < 2 * XBUFW; i += 256) dsm[i] = 0;
    __syncthreads();

    float acc[2][8][4];
    #pragma unroll
    for (int mf = 0; mf < 2; mf++)
        #pragma unroll
        for (int nf = 0; nf < 8; nf++)
            #pragma unroll
            for (int r = 0; r < 4; r++) acc[mf][nf][r] = 0.f;

    // ---- per-lane ldmatrix base addresses (byte offsets, buf-relative) ----
    const int lg = lane >> 3;   // lane group 0..3 -> x4 tile slot
    const int r8 = lane & 7;
    // A tiles: reg0 rows+0 k-lo | reg1 rows+8 k-lo | reg2 rows+0 k-hi | reg3 rows+8 k-hi
    const int mA = ((lg & 1) << 3) + r8;
    const int pieceA = lg >> 1;
    uint32_t aRel[2];
    #pragma unroll
    for (int mf = 0; mf < 2; mf++)
        aRel[mf] = ((row_out * 130 + x0 + mf * 16 + mA) * XPXW + pieceA * 4) * 4;
    // B tiles: reg0 oc+0 k-lo | reg1 oc+0 k-hi | reg2 oc+8 k-lo | reg3 oc+8 k-hi
    const int ocB = ((lg >> 1) << 3) + r8;
    const int pieceB = lg & 1;
    uint32_t bRel[4];
    #pragma unroll
    for (int p = 0; p < 4; p++)
        bRel[p] = ((p * 16 + ocB) * XPXW + pieceB * 4) * 4;

    auto stage = [&](int buf, int cc) {
        const uint32_t xdst = smem_u32 + (buf ? XBUFW * 4 : 0);
        const __half* xs = inb + cc * 16;
        #pragma unroll
        for (int i = tid; i < 1024; i += 256) {
            int row = i >> 8;
            int r = i & 255;
            int px = r >> 1;
            int piece = r & 1;
            int gy = y0 - 1 + row;
            if ((unsigned)gy < (unsigned)HH)
                cp_async16(xdst + (((row * 130) + px + 1) * XPXW + piece * 4) * 4,
                           xs + ((size_t)gy * WWID + px) * CIN + piece * 8);
        }
        const uint32_t wdst = smem_u32 + (2 * XBUFW + (buf ? WBUFW : 0)) * 4;
        const __half* ws = wsb + (size_t)cc * (9 * 64 * 16);
        #pragma unroll
        for (int i = tid; i < 1152; i += 256) {
            int row = i >> 1;
            int piece = i & 1;
            cp_async16(wdst + (row * XPXW + piece * 4) * 4,
                       ws + row * 16 + piece * 8);
        }
    };

    auto compute = [&](int buf) {
        const uint32_t xo = smem_u32 + (buf ? XBUFW * 4u : 0u);
        const uint32_t wo = smem_u32 + (2 * XBUFW + (buf ? WBUFW : 0)) * 4u;
        #pragma unroll
        for (int tap = 0; tap < 9; ++tap) {
            const int ky = tap / 3;
            const int kx = tap - ky * 3;
            const uint32_t tA = (uint32_t)((ky * 130 + kx) * XPXW * 4);
            uint32_t a[2][4];
            ldsm_x4(a[0], xo + aRel[0] + tA);
            ldsm_x4(a[1], xo + aRel[1] + tA);
            const uint32_t tB = wo + (uint32_t)(tap * 64 * XPXW * 4);
            #pragma unroll
            for (int p = 0; p < 4; p++) {
                uint32_t bf[4];
                ldsm_x4(bf, tB + bRel[p]);
                mma_f16(acc[0][2 * p], a[0], bf[0], bf[1]);
                mma_f16(acc[1][2 * p], a[1], bf[0], bf[1]);
                mma_f16(acc[0][2 * p + 1], a[0], bf[2], bf[3]);
                mma_f16(acc[1][2 * p + 1], a[1], bf[2], bf[3]);
            }
        }
    };

    stage(0, 0);
    cp_commit();
    int buf = 0;
    for (int cc = 0; cc < NC; ++cc) {
        if (cc + 1 < NC) stage(buf ^ 1, cc + 1);
        cp_commit();
        if (cc + 1 < NC) cp_wait1(); else cp_wait0();
        __syncthreads();
        compute(buf);
        __syncthreads();
        buf ^= 1;
    }

    if (MODE == 0) {
        // NHWC fp32 output (c2 stays full precision for sobel cancellation)
        float* out = outp + (size_t)b * HWSZ * C2;
        #pragma unroll
        for (int nf = 0; nf < 8; nf++) {
            int oc = ocb * 64 + nf * 8 + 2 * tig;
            float s0 = __ldg(&gg[oc]) * rsqrtf(__ldg(&vv[oc]) + EPSV);
            float t0 = (__ldg(&bb[oc]) - __ldg(&mm[oc])) * s0 + __ldg(&be[oc]);
            float s1 = __ldg(&gg[oc + 1]) * rsqrtf(__ldg(&vv[oc + 1]) + EPSV);
            float t1 = (__ldg(&bb[oc + 1]) - __ldg(&mm[oc + 1])) * s1 +
                       __ldg(&be[oc + 1]);
            #pragma unroll
            for (int mf = 0; mf < 2; mf++)
                #pragma unroll
                for (int h = 0; h < 2; h++) {
                    int px = (y0 + row_out) * WWID + x0 + mf * 16 + grp + h * 8;
                    float2 v;
                    v.x = fmaxf(fmaf(acc[mf][nf][h * 2 + 0], s0, t0), 0.f);
                    v.y = fmaxf(fmaf(acc[mf][nf][h * 2 + 1], s1, t1), 0.f);
                    *(float2*)(out + (size_t)px * C2 + oc) = v;
                }
        }
    } else {
        // NCHW fp32 output at channel offset 64, smem transpose for coalescing
        float* Csm = (float*)dsm;  // [256 px][stride 65]
        #pragma unroll
        for (int nf = 0; nf < 8; nf++) {
            int ocL = nf * 8 + 2 * tig;
            float s0 = __ldg(&gg[ocL]) * rsqrtf(__ldg(&vv[ocL]) + EPSV);
            float t0 =
                (__ldg(&bb[ocL]) - __ldg(&mm[ocL])) * s0 + __ldg(&be[ocL]);
            float s1 = __ldg(&gg[ocL + 1]) * rsqrtf(__ldg(&vv[ocL + 1]) + EPSV);
            float t1 = (__ldg(&bb[ocL + 1]) - __ldg(&mm[ocL + 1])) * s1 +
                       __ldg(&be[ocL + 1]);
            #pragma unroll
            for (int mf = 0; mf < 2; mf++)
                #pragma unroll
                for (int h = 0; h < 2; h++) {
                    int pxL = row_out * 128 + x0 + mf * 16 + grp + h * 8;
                    Csm[pxL * 65 + ocL] =
                        fmaxf(fmaf(acc[mf][nf][h * 2 + 0], s0, t0), 0.f);
                    Csm[pxL * 65 + ocL + 1] =
                        fmaxf(fmaf(acc[mf][nf][h * 2 + 1], s1, t1), 0.f);
                }
        }
        __syncthreads();
        #pragma unroll
        for (int i = 0; i < 8; i++) {
            int ocL = warp * 8 + i;
            float* op =
                outp + ((size_t)(b * 128 + 64 + ocL)) * HWSZ + y0 * WWID;
            #pragma unroll
            for (int c = 0; c < 8; c++) {
                int pxL = c * 32 + lane;
                op[pxL] = Csm[pxL * 65 + ocL];
            }
        }
    }
}

// ---------------------------------------------------------------------------
// sobel depthwise: NHWC fp32 in -> NHWC fp16 out (8 channels / thread)
// kernel (correlation): [[2,4,4],[-2,0,2],[-4,-4,-2]]
// ---------------------------------------------------------------------------
__global__ __launch_bounds__(256) void sobel_nhwc(const float* __restrict__ in,
                                                  __half* __restrict__ out) {
    int idx = blockIdx.x * 256 + threadIdx.x;  // B*HW*16 threads
    int cg = idx & 15;
    int x = (idx >> 4) & 127;
    int y = (idx >> 11) & 127;
    int b = idx >> 18;
    const float* base = in + ((size_t)b * HWSZ + y * WWID + x) * C2 + cg * 8;

    float acc[8];
    #pragma unroll
    for (int k = 0; k < 8; k++) acc[k] = 0.f;

    auto add = [&](int dy, int dx, float c) {
        int yy = y + dy, xx = x + dx;
        if ((unsigned)yy < (unsigned)HH && (unsigned)xx < (unsigned)WWID) {
            const float* p = base + (dy * WWID + dx) * C2;
            float4 v0 = *(const float4*)p;
            float4 v1 = *(const float4*)(p + 4);
            acc[0] = fmaf(c, v0.x, acc[0]);
            acc[1] = fmaf(c, v0.y, acc[1]);
            acc[2] = fmaf(c, v0.z, acc[2]);
            acc[3] = fmaf(c, v0.w, acc[3]);
            acc[4] = fmaf(c, v1.x, acc[4]);
            acc[5] = fmaf(c, v1.y, acc[5]);
            acc[6] = fmaf(c, v1.z, acc[6]);
            acc[7] = fmaf(c, v1.w, acc[7]);
        }
    };
    add(-1, -1, 2.f);  add(-1, 0, 4.f);  add(-1, 1, 4.f);
    add(0, -1, -2.f);                    add(0, 1, 2.f);
    add(1, -1, -4.f);  add(1, 0, -4.f);  add(1, 1, -2.f);

    __half2 r[4];
    #pragma unroll
    for (int k = 0; k < 4; k++)
        r[k] = __floats2half2_rn(acc[2 * k], acc[2 * k + 1]);
    *(uint4*)(out + ((size_t)b * HWSZ + y * WWID + x) * C2 + cg * 8) =
        *(uint4*)r;
}

// ---------------------------------------------------------------------------
__global__ __launch_bounds__(256) void concat_copy(const float4* __restrict__ in,
                                                   float4* __restrict__ out) {
    int idx = blockIdx.x * 256 + threadIdx.x;
    int b = idx >> 18;
    int r = idx & 262143;
    out[(size_t)b * 524288 + r] = in[(size_t)b * 262144 + r];
}

// ---------------------------------------------------------------------------
extern "C" void kernel_launch(void* const* d_in, const int* in_sizes, int n_in,
                              void* d_out, int out_size) {
    const float* input = (const float*)d_in[0];
    const float* w1 = (const float*)d_in[1];
    const float* b1 = (const float*)d_in[2];
    const float* g1 = (const float*)d_in[3];
    const float* be1 = (const float*)d_in[4];
    const float* m1 = (const float*)d_in[5];
    const float* v1 = (const float*)d_in[6];
    const float* w2 = (const float*)d_in[7];
    const float* b2 = (const float*)d_in[8];
    const float* g2 = (const float*)d_in[9];
    const float* be2 = (const float*)d_in[10];
    const float* m2 = (const float*)d_in[11];
    const float* v2 = (const float*)d_in[12];
    const float* w3 = (const float*)d_in[13];
    const float* b3 = (const float*)d_in[14];
    const float* g3 = (const float*)d_in[15];
    const float* be3 = (const float*)d_in[16];
    const float* m3 = (const float*)d_in[17];
    const float* v3 = (const float*)d_in[18];
    float* out = (float*)d_out;

    __half *c1h, *edgeh, *w2h, *w3h;
    float* c2f;
    uint32_t* w1t;
    cudaGetSymbolAddress((void**)&c1h, g_c1h);
    cudaGetSymbolAddress((void**)&c2f, g_c2f);
    cudaGetSymbolAddress((void**)&edgeh, g_edgeh);
    cudaGetSymbolAddress((void**)&w2h, g_w2h);
    cudaGetSymbolAddress((void**)&w3h, g_w3h);
    cudaGetSymbolAddress((void**)&w1t, g_w1t);

    static int attr_done = 0;
    if (!attr_done) {
        cudaFuncSetAttribute(conv1x1_mma_pipe,
                             cudaFuncAttributeMaxDynamicSharedMemorySize,
                             SMEM1X1_BYTES);
        cudaFuncSetAttribute(conv3x3_f16<C1, 0>,
                             cudaFuncAttributeMaxDynamicSharedMemorySize,
                             SMEMF16_BYTES);
        cudaFuncSetAttribute(conv3x3_f16<C2, 1>,
                             cudaFuncAttributeMaxDynamicSharedMemorySize,
                             SMEMF16_BYTES);
        attr_done = 1;
    }

    // weight prep
    prep_w1x1<<<(C1 * C_IN + 255) / 256, 256>>>(w1, w1t);
    prep_w3x3_h<<<(C2 * C1 * 9 + 255) / 256, 256>>>(w2, w2h, C2, C1);
    prep_w3x3_h<<<(C3 * C2 * 9 + 255) / 256, 256>>>(w3, w3h, C3, C2);

    // conv1: 1x1 64->256 (TF32) -> NHWC fp16
    conv1x1_mma_pipe<<<dim3(HWSZ / 256, C1 / 64, BATCH), 256, SMEM1X1_BYTES>>>(
        input, w1t, b1, g1, be1, m1, v1, c1h);

    // conv2: 3x3 256->128 (FP16 mma, ldmatrix) -> NHWC fp32
    conv3x3_f16<C1, 0><<<dim3(HH / 2, 2, BATCH), 256, SMEMF16_BYTES>>>(
        c1h, w2h, b2, g2, be2, m2, v2, c2f);

    // sobel depthwise (fp32 in -> fp16 out)
    sobel_nhwc<<<BATCH * HWSZ * (C2 / 8) / 256, 256>>>(c2f, edgeh);

    // conv3: 3x3 128->64 (FP16 mma, ldmatrix) -> out[:,64:128] NCHW fp32
    conv3x3_f16<C2, 1><<<dim3(HH / 2, 1, BATCH), 256, SMEMF16_BYTES>>>(
        edgeh, w3h, b3, g3, be3, m3, v3, out);

    // concat: out[:,0:64] = input
    concat_copy<<<BATCH * (C_IN * HWSZ / 4) / 256, 256>>>(
        (const float4*)input, (float4*)out);
}

// round 10
// speedup vs baseline: 5.8389x; 1.0022x over previous
#include <cuda_runtime.h>
#include <cuda_fp16.h>
#include <cstdint>

// ---------------------------------------------------------------------------
//   input:  [16, 64, 128, 128]  fp32 NCHW
//   conv1:  1x1, 64 -> 256, BN+ReLU  (TF32 mma)       -> c1  NHWC fp16
//   conv2:  3x3 pad1, 256 -> 128, BN+ReLU (FP16 mma)  -> c2  NHWC fp32
//   sobel:  depthwise 3x3 pad1 (summed kernel)        -> edge NHWC fp16
//   conv3:  3x3 pad1, 128 -> 64, BN+ReLU (FP16 mma)   -> out[:,64:128] NCHW f32
//   concat: out[:,0:64] = input
//
// R8 -> R9: conv3x3 fragment loads via ldmatrix.x4 (2 for A, 4 for B per tap)
// instead of 24 scalar LDS. Same fragments, bit-identical math.
// ---------------------------------------------------------------------------

#define BATCH 16
#define HH 128
#define WWID 128
#define HWSZ (HH * WWID)
#define C_IN 64
#define C1 256
#define C2 128
#define C3 64
#define EPSV 1e-5f

__device__ __align__(16) __half g_c1h[(size_t)BATCH * HWSZ * C1];    // 128 MB
__device__ __align__(16) float g_c2f[(size_t)BATCH * HWSZ * C2];     // 128 MB
__device__ __align__(16) __half g_edgeh[(size_t)BATCH * HWSZ * C2];  // 64 MB
__device__ __align__(16) __half g_w2h[2 * 16 * 9 * 64 * 16];  // [ocb][cc][tap][oc64][ic16]
__device__ __align__(16) __half g_w3h[1 * 8 * 9 * 64 * 16];
__device__ uint32_t g_w1t[4 * 8 * 8 * 64];                    // conv1 tf32 slab

// ---------------------------------------------------------------------------
// helpers
// ---------------------------------------------------------------------------
__device__ __forceinline__ uint32_t f2tf32(float x) {
    uint32_t r;
    asm("cvt.rna.tf32.f32 %0, %1;" : "=r"(r) : "f"(x));
    return r;
}
__device__ __forceinline__ uint32_t tf32_of_bits(uint32_t b) {
    return f2tf32(__uint_as_float(b));
}

__device__ __forceinline__ void mma_tf32(float c[4], const uint32_t a[4],
                                         uint32_t b0, uint32_t b1) {
    asm volatile(
        "mma.sync.aligned.m16n8k8.row.col.f32.tf32.tf32.f32 "
        "{%0,%1,%2,%3}, {%4,%5,%6,%7}, {%8,%9}, {%0,%1,%2,%3};"
        : "+f"(c[0]), "+f"(c[1]), "+f"(c[2]), "+f"(c[3])
        : "r"(a[0]), "r"(a[1]), "r"(a[2]), "r"(a[3]), "r"(b0), "r"(b1));
}

__device__ __forceinline__ void mma_f16(float c[4], const uint32_t a[4],
                                        uint32_t b0, uint32_t b1) {
    asm volatile(
        "mma.sync.aligned.m16n8k16.row.col.f32.f16.f16.f32 "
        "{%0,%1,%2,%3}, {%4,%5,%6,%7}, {%8,%9}, {%0,%1,%2,%3};"
        : "+f"(c[0]), "+f"(c[1]), "+f"(c[2]), "+f"(c[3])
        : "r"(a[0]), "r"(a[1]), "r"(a[2]), "r"(a[3]), "r"(b0), "r"(b1));
}

__device__ __forceinline__ void ldsm_x4(uint32_t r[4], uint32_t addr) {
    asm volatile(
        "ldmatrix.sync.aligned.m8n8.x4.shared.b16 {%0,%1,%2,%3}, [%4];"
        : "=r"(r[0]), "=r"(r[1]), "=r"(r[2]), "=r"(r[3])
        : "r"(addr));
}

__device__ __forceinline__ void cp_async16(uint32_t dst, const void* src) {
    asm volatile("cp.async.cg.shared.global [%0], [%1], 16;\n" ::"r"(dst),
                 "l"(src));
}
__device__ __forceinline__ void cp_commit() {
    asm volatile("cp.async.commit_group;\n" ::: "memory");
}
__device__ __forceinline__ void cp_wait1() {
    asm volatile("cp.async.wait_group 1;\n" ::: "memory");
}
__device__ __forceinline__ void cp_wait0() {
    asm volatile("cp.async.wait_group 0;\n" ::: "memory");
}

// ---------------------------------------------------------------------------
// weight prep
// ---------------------------------------------------------------------------
__global__ void prep_w3x3_h(const float* __restrict__ w,
                            __half* __restrict__ o, int OC, int CIN) {
    int t = blockIdx.x * 256 + threadIdx.x;
    int total = OC * CIN * 9;
    if (t >= total) return;
    int oc = t / (CIN * 9);
    int r = t - oc * (CIN * 9);
    int ic = r / 9;
    int tap = r - ic * 9;
    int ocb = oc >> 6, oc64 = oc & 63;
    int cc = ic >> 4, icr = ic & 15;
    int NC = CIN / 16;
    o[((((size_t)ocb * NC + cc) * 9 + tap) * 64 + oc64) * 16 + icr] =
        __float2half(w[t]);
}

__global__ void prep_w1x1(const float* __restrict__ w,
                          uint32_t* __restrict__ o) {
    int t = blockIdx.x * 256 + threadIdx.x;
    if (t >= C1 * C_IN) return;
    int oc = t / C_IN;
    int ic = t - oc * C_IN;
    int ocb = oc >> 6, oc64 = oc & 63;
    int cc = ic >> 3, icr = ic & 7;
    o[(((size_t)ocb * 8 + cc) * 8 + icr) * 64 + oc64] = f2tf32(w[t]);
}

// ---------------------------------------------------------------------------
// conv1: 1x1 64->256, TF32 mma, cp.async pipelined -> NHWC fp16
// ---------------------------------------------------------------------------
#define X1_BUF_W 2112  // 8*264
#define W1_BUF_W 576   // 8*72
#define SMEM1X1_BYTES ((2 * X1_BUF_W + 2 * W1_BUF_W) * 4)

__global__ __launch_bounds__(256, 2) void conv1x1_mma_pipe(
    const float* __restrict__ x, const uint32_t* __restrict__ wslab,
    const float* __restrict__ bb, const float* __restrict__ gg,
    const float* __restrict__ be, const float* __restrict__ mm,
    const float* __restrict__ vv, __half* __restrict__ out) {
    constexpr int NC = 8;
    extern __shared__ uint32_t dsm[];
    uint32_t* Xb[2] = {dsm, dsm + X1_BUF_W};
    uint32_t* Wb[2] = {dsm + 2 * X1_BUF_W, dsm + 2 * X1_BUF_W + W1_BUF_W};
    const uint32_t smem_u32 = (uint32_t)__cvta_generic_to_shared((void*)dsm);

    const int pxBase = blockIdx.x * 256;
    const int ocb = blockIdx.y;
    const int b = blockIdx.z;
    const int tid = threadIdx.x;
    const int lane = tid & 31;
    const int warp = tid >> 5;

    const int wm = warp >> 2;
    const int wn = warp & 3;
    const int px0 = wn * 64;
    const int tig = lane & 3;
    const int grp = lane >> 2;

    const float* xb = x + (size_t)b * C_IN * HWSZ + pxBase;
    const uint32_t* ws_base = wslab + (size_t)ocb * NC * (8 * 64);

    float acc[2][8][4];
    #pragma unroll
    for (int mf = 0; mf < 2; mf++)
        #pragma unroll
        for (int nf = 0; nf < 8; nf++)
            #pragma unroll
            for (int r = 0; r < 4; r++) acc[mf][nf][r] = 0.f;

    auto stage = [&](int buf, int cc) {
        const uint32_t xdst0 = smem_u32 + (buf ? X1_BUF_W * 4 : 0);
        const float* src = xb + (size_t)(cc * 8) * HWSZ;
        #pragma unroll
        for (int i = tid; i < 8 * 64; i += 256) {
            int ic = i >> 6;
            int piece = i & 63;
            cp_async16(xdst0 + (ic * 264 + piece * 4) * 4,
                       src + (size_t)ic * HWSZ + piece * 4);
        }
        const uint32_t wdst0 =
            smem_u32 + (2 * X1_BUF_W + (buf ? W1_BUF_W : 0)) * 4;
        const uint32_t* ws = ws_base + (size_t)cc * (8 * 64);
        if (tid < 128) {
            int row = tid >> 4;
            int piece = tid & 15;
            cp_async16(wdst0 + (row * 72 + piece * 4) * 4,
                       ws + row * 64 + piece * 4);
        }
    };

    auto compute = [&](int buf) {
        const uint32_t* pB = Xb[buf] + tig * 264 + px0 + grp;
        const uint32_t* pA = Wb[buf] + tig * 72 + wm * 32 + grp;
        uint32_t a[2][4];
        #pragma unroll
        for (int mf = 0; mf < 2; mf++) {
            const int base = mf * 16;
            a[mf][0] = pA[base];
            a[mf][1] = pA[base + 8];
            a[mf][2] = pA[base + 288];
            a[mf][3] = pA[base + 296];
        }
        #pragma unroll
        for (int nf = 0; nf < 8; nf++) {
            uint32_t b0 = tf32_of_bits(pB[nf * 8]);
            uint32_t b1 = tf32_of_bits(pB[1056 + nf * 8]);
            mma_tf32(acc[0][nf], a[0], b0, b1);
            mma_tf32(acc[1][nf], a[1], b0, b1);
        }
    };

    stage(0, 0);
    cp_commit();
    int buf = 0;
    for (int cc = 0; cc < NC; ++cc) {
        if (cc + 1 < NC) stage(buf ^ 1, cc + 1);
        cp_commit();
        if (cc + 1 < NC) cp_wait1(); else cp_wait0();
        __syncthreads();
        compute(buf);
        __syncthreads();
        buf ^= 1;
    }

    // epilogue: BN + ReLU -> NHWC fp16
    #pragma unroll
    for (int mf = 0; mf < 2; mf++) {
        #pragma unroll
        for (int rr = 0; rr < 2; rr++) {
            int oc = ocb * 64 + wm * 32 + mf * 16 + grp + rr * 8;
            float s = __ldg(&gg[oc]) * rsqrtf(__ldg(&vv[oc]) + EPSV);
            float t = (__ldg(&bb[oc]) - __ldg(&mm[oc])) * s + __ldg(&be[oc]);
            #pragma unroll
            for (int nf = 0; nf < 8; nf++) {
                float v0 = fmaxf(fmaf(acc[mf][nf][rr * 2 + 0], s, t), 0.f);
                float v1 = fmaxf(fmaf(acc[mf][nf][rr * 2 + 1], s, t), 0.f);
                int pxl = pxBase + px0 + nf * 8 + tig * 2;
                __half* dst = out + ((size_t)b * HWSZ + pxl) * C1 + oc;
                dst[0] = __float2half(v0);
                dst[C1] = __float2half(v1);
            }
        }
    }
}

// ---------------------------------------------------------------------------
// conv3x3 fp16 implicit GEMM, ldmatrix fragment loads.
// CTA: 256 px (2 output rows) x 64 oc. 8 warps: warp = m32 x n64.
// X smem: [4 rows][130 px][12 words]; W smem: [9 tap][64 oc][12 words].
// Row stride 48B -> ldmatrix phases hit all 32 banks (12k mod 32 distinct).
// MODE 0: out NHWC fp32 (C=128).  MODE 1: out NCHW fp32, ch offset 64.
// ---------------------------------------------------------------------------
#define XPXW 12
#define XROWW (130 * XPXW)
#define XBUFW (4 * XROWW)          // 6240
#define WBUFW (576 * XPXW)         // 6912
#define SMEMF16_WORDS (2 * XBUFW + 2 * WBUFW)
#define SMEMF16_BYTES (SMEMF16_WORDS * 4)

template <int CIN, int MODE>
__global__ __launch_bounds__(256, 2) void conv3x3_f16(
    const __half* __restrict__ in, const __half* __restrict__ wslab,
    const float* __restrict__ bb, const float* __restrict__ gg,
    const float* __restrict__ be, const float* __restrict__ mm,
    const float* __restrict__ vv, float* __restrict__ outp) {
    constexpr int NC = CIN / 16;
    extern __shared__ uint32_t dsm[];
    const uint32_t smem_u32 = (uint32_t)__cvta_generic_to_shared((void*)dsm);

    const int y0 = blockIdx.x * 2;
    const int ocb = blockIdx.y;
    const int b = blockIdx.z;
    const int tid = threadIdx.x;
    const int lane = tid & 31;
    const int warp = tid >> 5;
    const int row_out = warp >> 2;
    const int x0 = (warp & 3) * 32;
    const int grp = lane >> 2;
    const int tig = lane & 3;

    const __half* inb = in + (size_t)b * HWSZ * CIN;
    const __half* wsb = wslab + (size_t)ocb * ((size_t)NC * 9 * 64 * 16);

    // zero X halo regions once, then barrier before any cp.async can land
    for (int i = tid; i < 2 * XBUFW; i += 256) dsm[i] = 0;
    __syncthreads();

    float acc[2][8][4];
    #pragma unroll
    for (int mf = 0; mf < 2; mf++)
        #pragma unroll
        for (int nf = 0; nf < 8; nf++)
            #pragma unroll
            for (int r = 0; r < 4; r++) acc[mf][nf][r] = 0.f;

    // ---- per-lane ldmatrix base addresses (byte offsets, buf-relative) ----
    const int lg = lane >> 3;   // lane group 0..3 -> x4 tile slot
    const int r8 = lane & 7;
    // A tiles: reg0 rows+0 k-lo | reg1 rows+8 k-lo | reg2 rows+0 k-hi | reg3 rows+8 k-hi
    const int mA = ((lg & 1) << 3) + r8;
    const int pieceA = lg >> 1;
    uint32_t aRel[2];
    #pragma unroll
    for (int mf = 0; mf < 2; mf++)
        aRel[mf] = ((row_out * 130 + x0 + mf * 16 + mA) * XPXW + pieceA * 4) * 4;
    // B tiles: reg0 oc+0 k-lo | reg1 oc+0 k-hi | reg2 oc+8 k-lo | reg3 oc+8 k-hi
    const int ocB = ((lg >> 1) << 3) + r8;
    const int pieceB = lg & 1;
    uint32_t bRel[4];
    #pragma unroll
    for (int p = 0; p < 4; p++)
        bRel[p] = ((p * 16 + ocB) * XPXW + pieceB * 4) * 4;

    auto stage = [&](int buf, int cc) {
        const uint32_t xdst = smem_u32 + (buf ? XBUFW * 4 : 0);
        const __half* xs = inb + cc * 16;
        #pragma unroll
        for (int i = tid; i < 1024; i += 256) {
            int row = i >> 8;
            int r = i & 255;
            int px = r >> 1;
            int piece = r & 1;
            int gy = y0 - 1 + row;
            if ((unsigned)gy < (unsigned)HH)
                cp_async16(xdst + (((row * 130) + px + 1) * XPXW + piece * 4) * 4,
                           xs + ((size_t)gy * WWID + px) * CIN + piece * 8);
        }
        const uint32_t wdst = smem_u32 + (2 * XBUFW + (buf ? WBUFW : 0)) * 4;
        const __half* ws = wsb + (size_t)cc * (9 * 64 * 16);
        #pragma unroll
        for (int i = tid; i < 1152; i += 256) {
            int row = i >> 1;
            int piece = i & 1;
            cp_async16(wdst + (row * XPXW + piece * 4) * 4,
                       ws + row * 16 + piece * 8);
        }
    };

    auto compute = [&](int buf) {
        const uint32_t xo = smem_u32 + (buf ? XBUFW * 4u : 0u);
        const uint32_t wo = smem_u32 + (2 * XBUFW + (buf ? WBUFW : 0)) * 4u;
        #pragma unroll
        for (int tap = 0; tap < 9; ++tap) {
            const int ky = tap / 3;
            const int kx = tap - ky * 3;
            const uint32_t tA = (uint32_t)((ky * 130 + kx) * XPXW * 4);
            uint32_t a[2][4];
            ldsm_x4(a[0], xo + aRel[0] + tA);
            ldsm_x4(a[1], xo + aRel[1] + tA);
            const uint32_t tB = wo + (uint32_t)(tap * 64 * XPXW * 4);
            #pragma unroll
            for (int p = 0; p < 4; p++) {
                uint32_t bf[4];
                ldsm_x4(bf, tB + bRel[p]);
                mma_f16(acc[0][2 * p], a[0], bf[0], bf[1]);
                mma_f16(acc[1][2 * p], a[1], bf[0], bf[1]);
                mma_f16(acc[0][2 * p + 1], a[0], bf[2], bf[3]);
                mma_f16(acc[1][2 * p + 1], a[1], bf[2], bf[3]);
            }
        }
    };

    stage(0, 0);
    cp_commit();
    int buf = 0;
    for (int cc = 0; cc < NC; ++cc) {
        if (cc + 1 < NC) stage(buf ^ 1, cc + 1);
        cp_commit();
        if (cc + 1 < NC) cp_wait1(); else cp_wait0();
        __syncthreads();
        compute(buf);
        __syncthreads();
        buf ^= 1;
    }

    if (MODE == 0) {
        // NHWC fp32 output (c2 stays full precision for sobel cancellation)
        float* out = outp + (size_t)b * HWSZ * C2;
        #pragma unroll
        for (int nf = 0; nf < 8; nf++) {
            int oc = ocb * 64 + nf * 8 + 2 * tig;
            float s0 = __ldg(&gg[oc]) * rsqrtf(__ldg(&vv[oc]) + EPSV);
            float t0 = (__ldg(&bb[oc]) - __ldg(&mm[oc])) * s0 + __ldg(&be[oc]);
            float s1 = __ldg(&gg[oc + 1]) * rsqrtf(__ldg(&vv[oc + 1]) + EPSV);
            float t1 = (__ldg(&bb[oc + 1]) - __ldg(&mm[oc + 1])) * s1 +
                       __ldg(&be[oc + 1]);
            #pragma unroll
            for (int mf = 0; mf < 2; mf++)
                #pragma unroll
                for (int h = 0; h < 2; h++) {
                    int px = (y0 + row_out) * WWID + x0 + mf * 16 + grp + h * 8;
                    float2 v;
                    v.x = fmaxf(fmaf(acc[mf][nf][h * 2 + 0], s0, t0), 0.f);
                    v.y = fmaxf(fmaf(acc[mf][nf][h * 2 + 1], s1, t1), 0.f);
                    *(float2*)(out + (size_t)px * C2 + oc) = v;
                }
        }
    } else {
        // NCHW fp32 output at channel offset 64, smem transpose for coalescing
        float* Csm = (float*)dsm;  // [256 px][stride 65]
        #pragma unroll
        for (int nf = 0; nf < 8; nf++) {
            int ocL = nf * 8 + 2 * tig;
            float s0 = __ldg(&gg[ocL]) * rsqrtf(__ldg(&vv[ocL]) + EPSV);
            float t0 =
                (__ldg(&bb[ocL]) - __ldg(&mm[ocL])) * s0 + __ldg(&be[ocL]);
            float s1 = __ldg(&gg[ocL + 1]) * rsqrtf(__ldg(&vv[ocL + 1]) + EPSV);
            float t1 = (__ldg(&bb[ocL + 1]) - __ldg(&mm[ocL + 1])) * s1 +
                       __ldg(&be[ocL + 1]);
            #pragma unroll
            for (int mf = 0; mf < 2; mf++)
                #pragma unroll
                for (int h = 0; h < 2; h++) {
                    int pxL = row_out * 128 + x0 + mf * 16 + grp + h * 8;
                    Csm[pxL * 65 + ocL] =
                        fmaxf(fmaf(acc[mf][nf][h * 2 + 0], s0, t0), 0.f);
                    Csm[pxL * 65 + ocL + 1] =
                        fmaxf(fmaf(acc[mf][nf][h * 2 + 1], s1, t1), 0.f);
                }
        }
        __syncthreads();
        #pragma unroll
        for (int i = 0; i < 8; i++) {
            int ocL = warp * 8 + i;
            float* op =
                outp + ((size_t)(b * 128 + 64 + ocL)) * HWSZ + y0 * WWID;
            #pragma unroll
            for (int c = 0; c < 8; c++) {
                int pxL = c * 32 + lane;
                op[pxL] = Csm[pxL * 65 + ocL];
            }
        }
    }
}

// ---------------------------------------------------------------------------
// sobel depthwise: NHWC fp32 in -> NHWC fp16 out (8 channels / thread)
// kernel (correlation): [[2,4,4],[-2,0,2],[-4,-4,-2]]
// ---------------------------------------------------------------------------
__global__ __launch_bounds__(256) void sobel_nhwc(const float* __restrict__ in,
                                                  __half* __restrict__ out) {
    int idx = blockIdx.x * 256 + threadIdx.x;  // B*HW*16 threads
    int cg = idx & 15;
    int x = (idx >> 4) & 127;
    int y = (idx >> 11) & 127;
    int b = idx >> 18;
    const float* base = in + ((size_t)b * HWSZ + y * WWID + x) * C2 + cg * 8;

    float acc[8];
    #pragma unroll
    for (int k = 0; k < 8; k++) acc[k] = 0.f;

    auto add = [&](int dy, int dx, float c) {
        int yy = y + dy, xx = x + dx;
        if ((unsigned)yy < (unsigned)HH && (unsigned)xx < (unsigned)WWID) {
            const float* p = base + (dy * WWID + dx) * C2;
            float4 v0 = *(const float4*)p;
            float4 v1 = *(const float4*)(p + 4);
            acc[0] = fmaf(c, v0.x, acc[0]);
            acc[1] = fmaf(c, v0.y, acc[1]);
            acc[2] = fmaf(c, v0.z, acc[2]);
            acc[3] = fmaf(c, v0.w, acc[3]);
            acc[4] = fmaf(c, v1.x, acc[4]);
            acc[5] = fmaf(c, v1.y, acc[5]);
            acc[6] = fmaf(c, v1.z, acc[6]);
            acc[7] = fmaf(c, v1.w, acc[7]);
        }
    };
    add(-1, -1, 2.f);  add(-1, 0, 4.f);  add(-1, 1, 4.f);
    add(0, -1, -2.f);                    add(0, 1, 2.f);
    add(1, -1, -4.f);  add(1, 0, -4.f);  add(1, 1, -2.f);

    __half2 r[4];
    #pragma unroll
    for (int k = 0; k < 4; k++)
        r[k] = __floats2half2_rn(acc[2 * k], acc[2 * k + 1]);
    *(uint4*)(out + ((size_t)b * HWSZ + y * WWID + x) * C2 + cg * 8) =
        *(uint4*)r;
}

// ---------------------------------------------------------------------------
__global__ __launch_bounds__(256) void concat_copy(const float4* __restrict__ in,
                                                   float4* __restrict__ out) {
    int idx = blockIdx.x * 256 + threadIdx.x;
    int b = idx >> 18;
    int r = idx & 262143;
    out[(size_t)b * 524288 + r] = in[(size_t)b * 262144 + r];
}

// ---------------------------------------------------------------------------
extern "C" void kernel_launch(void* const* d_in, const int* in_sizes, int n_in,
                              void* d_out, int out_size) {
    const float* input = (const float*)d_in[0];
    const float* w1 = (const float*)d_in[1];
    const float* b1 = (const float*)d_in[2];
    const float* g1 = (const float*)d_in[3];
    const float* be1 = (const float*)d_in[4];
    const float* m1 = (const float*)d_in[5];
    const float* v1 = (const float*)d_in[6];
    const float* w2 = (const float*)d_in[7];
    const float* b2 = (const float*)d_in[8];
    const float* g2 = (const float*)d_in[9];
    const float* be2 = (const float*)d_in[10];
    const float* m2 = (const float*)d_in[11];
    const float* v2 = (const float*)d_in[12];
    const float* w3 = (const float*)d_in[13];
    const float* b3 = (const float*)d_in[14];
    const float* g3 = (const float*)d_in[15];
    const float* be3 = (const float*)d_in[16];
    const float* m3 = (const float*)d_in[17];
    const float* v3 = (const float*)d_in[18];
    float* out = (float*)d_out;

    __half *c1h, *edgeh, *w2h, *w3h;
    float* c2f;
    uint32_t* w1t;
    cudaGetSymbolAddress((void**)&c1h, g_c1h);
    cudaGetSymbolAddress((void**)&c2f, g_c2f);
    cudaGetSymbolAddress((void**)&edgeh, g_edgeh);
    cudaGetSymbolAddress((void**)&w2h, g_w2h);
    cudaGetSymbolAddress((void**)&w3h, g_w3h);
    cudaGetSymbolAddress((void**)&w1t, g_w1t);

    static int attr_done = 0;
    if (!attr_done) {
        cudaFuncSetAttribute(conv1x1_mma_pipe,
                             cudaFuncAttributeMaxDynamicSharedMemorySize,
                             SMEM1X1_BYTES);
        cudaFuncSetAttribute(conv3x3_f16<C1, 0>,
                             cudaFuncAttributeMaxDynamicSharedMemorySize,
                             SMEMF16_BYTES);
        cudaFuncSetAttribute(conv3x3_f16<C2, 1>,
                             cudaFuncAttributeMaxDynamicSharedMemorySize,
                             SMEMF16_BYTES);
        attr_done = 1;
    }

    // weight prep
    prep_w1x1<<<(C1 * C_IN + 255) / 256, 256>>>(w1, w1t);
    prep_w3x3_h<<<(C2 * C1 * 9 + 255) / 256, 256>>>(w2, w2h, C2, C1);
    prep_w3x3_h<<<(C3 * C2 * 9 + 255) / 256, 256>>>(w3, w3h, C3, C2);

    // conv1: 1x1 64->256 (TF32) -> NHWC fp16
    conv1x1_mma_pipe<<<dim3(HWSZ / 256, C1 / 64, BATCH), 256, SMEM1X1_BYTES>>>(
        input, w1t, b1, g1, be1, m1, v1, c1h);

    // conv2: 3x3 256->128 (FP16 mma, ldmatrix) -> NHWC fp32
    conv3x3_f16<C1, 0><<<dim3(HH / 2, 2, BATCH), 256, SMEMF16_BYTES>>>(
        c1h, w2h, b2, g2, be2, m2, v2, c2f);

    // sobel depthwise (fp32 in -> fp16 out)
    sobel_nhwc<<<BATCH * HWSZ * (C2 / 8) / 256, 256>>>(c2f, edgeh);

    // conv3: 3x3 128->64 (FP16 mma, ldmatrix) -> out[:,64:128] NCHW fp32
    conv3x3_f16<C2, 1><<<dim3(HH / 2, 1, BATCH), 256, SMEMF16_BYTES>>>(
        edgeh, w3h, b3, g3, be3, m3, v3, out);

    // concat: out[:,0:64] = input
    concat_copy<<<BATCH * (C_IN * HWSZ / 4) / 256, 256>>>(
        (const float4*)input, (float4*)out);
}